// round 9
// baseline (speedup 1.0000x reference)
#include <cuda_runtime.h>

#define PP 32768
#define LL 16
#define KK 8
#define HH 128

// Full h buffer for all L*P nodes (pred holds GLOBAL indices). 256 MiB static.
__device__ float g_h[(long long)LL * PP * HH];

__device__ __forceinline__ float lrelu(float x) { return x > 0.0f ? x : 0.1f * x; }
__device__ __forceinline__ float relu_(float x) { return x > 0.0f ? x : 0.0f; }

// bank swizzle for 32-row tiles: float4-index XOR'd by row bits [2:5)
__device__ __forceinline__ int swz(int r) { return (r >> 2) & 7; }

// ---------------------------------------------------------------------------
// h[0:P] = mlp2(delay, pi)   (unchanged)
// ---------------------------------------------------------------------------
__global__ void __launch_bounds__(256, 1)
k_init(const float* __restrict__ delay,
       const float* __restrict__ w1, const float* __restrict__ b1,
       const float* __restrict__ w2, const float* __restrict__ b2)
{
    extern __shared__ float smem[];
    float* s_t1 = smem;            // 64*64
    float* s_w2 = s_t1 + 64 * 64;  // 64*128
    float* s_b2 = s_w2 + 64 * 128; // 128

    const int tid  = threadIdx.x;
    const int row0 = blockIdx.x * 64;

    for (int i = tid; i < (64 * 128) / 4; i += 256)
        ((float4*)s_w2)[i] = ((const float4*)w2)[i];
    for (int i = tid; i < 128; i += 256) s_b2[i] = b2[i];
    for (int i = tid; i < 64 * 64; i += 256) {
        int r = i >> 6, c = i & 63;
        s_t1[i] = lrelu(delay[row0 + r] * w1[c] + b1[c]);
    }
    __syncthreads();

    const int w = tid >> 5, l = tid & 31;
    const int r0 = w * 8, c0 = l * 4;
    float acc[8][4];
#pragma unroll
    for (int r = 0; r < 8; r++)
#pragma unroll
        for (int c = 0; c < 4; c++) acc[r][c] = 0.0f;

#pragma unroll 4
    for (int k = 0; k < 64; k += 2) {
        float4 w0  = *(const float4*)(s_w2 + k * 128 + c0);
        float4 w1v = *(const float4*)(s_w2 + (k + 1) * 128 + c0);
#pragma unroll
        for (int r = 0; r < 8; r++) {
            float2 a = *(const float2*)(s_t1 + (r0 + r) * 64 + k);
            acc[r][0] = fmaf(a.x, w0.x, acc[r][0]); acc[r][0] = fmaf(a.y, w1v.x, acc[r][0]);
            acc[r][1] = fmaf(a.x, w0.y, acc[r][1]); acc[r][1] = fmaf(a.y, w1v.y, acc[r][1]);
            acc[r][2] = fmaf(a.x, w0.z, acc[r][2]); acc[r][2] = fmaf(a.y, w1v.z, acc[r][2]);
            acc[r][3] = fmaf(a.x, w0.w, acc[r][3]); acc[r][3] = fmaf(a.y, w1v.w, acc[r][3]);
        }
    }
#pragma unroll
    for (int r = 0; r < 8; r++) {
        float4 o;
        o.x = acc[r][0] + s_b2[c0 + 0];
        o.y = acc[r][1] + s_b2[c0 + 1];
        o.z = acc[r][2] + s_b2[c0 + 2];
        o.w = acc[r][3] + s_b2[c0 + 3];
        *(float4*)(g_h + (long long)(row0 + r0 + r) * HH + c0) = o;
    }
}

// ---------------------------------------------------------------------------
// Layer i (i=1..15). 128 thr / 32 rows / block, 22.5KB smem, 7 blocks/SM,
// grid 1024 single-wave. Warps split COLUMNS: each weight LDG serves the
// whole 32-row tile (1 wavefront/k). s_nt/s_ft accesses XOR-swizzled so
// multi-row reads are bank-conflict-free. Weights direct-from-global.
// ---------------------------------------------------------------------------
template <bool DO_RELU>
__global__ void __launch_bounds__(128, 7)
k_layer(int lo,
        const int*   __restrict__ pred,   // this layer's slice: PP*KK
        const float* __restrict__ feat,
        const float* __restrict__ ne_w1, const float* __restrict__ ne_b1,
        const float* __restrict__ ne_w2, const float* __restrict__ ne_b2,
        const float* __restrict__ sf_w1, const float* __restrict__ sf_b1,
        const float* __restrict__ sf_w2, const float* __restrict__ sf_b2)
{
    extern __shared__ float smem[];
    float* s_nt  = smem;            // 32*128 = 4096 floats (neigh, then t) SWIZZLED
    float* s_ft  = smem + 4096;     // 32*32 = 1024 SWIZZLED
    float* s_b1  = smem + 5120;     // 128
    float* s_b2  = smem + 5248;     // 128
    int*   s_pred = (int*)(smem + 5376);  // 256 ints
    // total 5632 floats = 22528 B
    float4* nt4 = (float4*)s_nt;    // pitch 32 float4
    float4* ft4 = (float4*)s_ft;    // pitch 8 float4

    const int tid  = threadIdx.x;
    const int row0 = blockIdx.x * 32;

    // ---- preload ft (swizzled), pred, biases ----
    for (int i = tid; i < 256; i += 128) {
        int r = i >> 3, c4 = i & 7;
        ft4[r * 8 + (c4 ^ swz(r))] =
            *((const float4*)(feat + (long long)(lo + row0 + r) * 32) + c4);
    }
    for (int i = tid; i < 256; i += 128)
        s_pred[i] = pred[(long long)row0 * KK + i];
    if (tid < 128) {
        s_b1[tid] = (tid < 64) ? ne_b1[tid] : sf_b1[tid - 64];
        s_b2[tid] = ne_b2[tid] + sf_b2[tid];
    }
    __syncthreads();

    // ---- gather mean of 8 predecessor rows (swizzled store) ----
#pragma unroll
    for (int j = 0; j < 8; j++) {
        int task = tid + j * 128;
        int r = task >> 5, c4 = task & 31;
        const int* pr = s_pred + r * 8;
        float x = 0.f, y = 0.f, z = 0.f, ww = 0.f;
#pragma unroll
        for (int k = 0; k < 8; k++) {
            const float4 v = *((const float4*)(g_h + (long long)pr[k] * HH) + c4);
            x += v.x; y += v.y; z += v.z; ww += v.w;
        }
        nt4[r * 32 + (c4 ^ swz(r))] =
            make_float4(x * 0.125f, y * 0.125f, z * 0.125f, ww * 0.125f);
    }
    __syncthreads();

    const int w = tid >> 5, l = tid & 31;
    // stage-1 lane map: 4 rowgroups x dup x 4 colgroups
    const int rg1 = l >> 3;          // 0..3
    const int dup = (l >> 2) & 1;    // 0..1
    const int cg  = l & 3;           // 0..3
    const int cn  = w * 16 + cg * 4; // ne/sf hidden col base (0..63)
    const int r1b = rg1 * 8 + dup * 4;
    // stage-2 lane map: 4 rowgroups x 8 col4s
    const int rg2 = l >> 3;
    const int cc  = l & 7;
    const int c0  = w * 32 + cc * 4; // out col base (0..127)

    // ---- stage 1, ne path: k=128, warp owns 16 hidden cols of all 32 rows ----
    float acc1[4][4], acc2[4][4];
#pragma unroll
    for (int i = 0; i < 4; i++)
#pragma unroll
        for (int c = 0; c < 4; c++) { acc1[i][c] = 0.f; acc2[i][c] = 0.f; }

#pragma unroll 4
    for (int k = 0; k < 128; k += 4) {
        float4 wv0 = *(const float4*)(ne_w1 + (k + 0) * 64 + cn);
        float4 wv1 = *(const float4*)(ne_w1 + (k + 1) * 64 + cn);
        float4 wv2 = *(const float4*)(ne_w1 + (k + 2) * 64 + cn);
        float4 wv3 = *(const float4*)(ne_w1 + (k + 3) * 64 + cn);
#pragma unroll
        for (int i = 0; i < 4; i++) {
            const int R = r1b + i;
            float4 a = nt4[R * 32 + ((k >> 2) ^ swz(R))];
            acc1[i][0] = fmaf(a.x, wv0.x, acc1[i][0]); acc1[i][0] = fmaf(a.y, wv1.x, acc1[i][0]);
            acc1[i][0] = fmaf(a.z, wv2.x, acc1[i][0]); acc1[i][0] = fmaf(a.w, wv3.x, acc1[i][0]);
            acc1[i][1] = fmaf(a.x, wv0.y, acc1[i][1]); acc1[i][1] = fmaf(a.y, wv1.y, acc1[i][1]);
            acc1[i][1] = fmaf(a.z, wv2.y, acc1[i][1]); acc1[i][1] = fmaf(a.w, wv3.y, acc1[i][1]);
            acc1[i][2] = fmaf(a.x, wv0.z, acc1[i][2]); acc1[i][2] = fmaf(a.y, wv1.z, acc1[i][2]);
            acc1[i][2] = fmaf(a.z, wv2.z, acc1[i][2]); acc1[i][2] = fmaf(a.w, wv3.z, acc1[i][2]);
            acc1[i][3] = fmaf(a.x, wv0.w, acc1[i][3]); acc1[i][3] = fmaf(a.y, wv1.w, acc1[i][3]);
            acc1[i][3] = fmaf(a.z, wv2.w, acc1[i][3]); acc1[i][3] = fmaf(a.w, wv3.w, acc1[i][3]);
        }
    }

    // ---- stage 1, sf path: k=32 over swizzled s_ft ----
#pragma unroll 2
    for (int k = 0; k < 32; k += 4) {
        float4 wv0 = *(const float4*)(sf_w1 + (k + 0) * 64 + cn);
        float4 wv1 = *(const float4*)(sf_w1 + (k + 1) * 64 + cn);
        float4 wv2 = *(const float4*)(sf_w1 + (k + 2) * 64 + cn);
        float4 wv3 = *(const float4*)(sf_w1 + (k + 3) * 64 + cn);
#pragma unroll
        for (int i = 0; i < 4; i++) {
            const int R = r1b + i;
            float4 a = ft4[R * 8 + ((k >> 2) ^ swz(R))];
            acc2[i][0] = fmaf(a.x, wv0.x, acc2[i][0]); acc2[i][0] = fmaf(a.y, wv1.x, acc2[i][0]);
            acc2[i][0] = fmaf(a.z, wv2.x, acc2[i][0]); acc2[i][0] = fmaf(a.w, wv3.x, acc2[i][0]);
            acc2[i][1] = fmaf(a.x, wv0.y, acc2[i][1]); acc2[i][1] = fmaf(a.y, wv1.y, acc2[i][1]);
            acc2[i][1] = fmaf(a.z, wv2.y, acc2[i][1]); acc2[i][1] = fmaf(a.w, wv3.y, acc2[i][1]);
            acc2[i][2] = fmaf(a.x, wv0.z, acc2[i][2]); acc2[i][2] = fmaf(a.y, wv1.z, acc2[i][2]);
            acc2[i][2] = fmaf(a.z, wv2.z, acc2[i][2]); acc2[i][2] = fmaf(a.w, wv3.z, acc2[i][2]);
            acc2[i][3] = fmaf(a.x, wv0.w, acc2[i][3]); acc2[i][3] = fmaf(a.y, wv1.w, acc2[i][3]);
            acc2[i][3] = fmaf(a.z, wv2.w, acc2[i][3]); acc2[i][3] = fmaf(a.w, wv3.w, acc2[i][3]);
        }
    }
    __syncthreads();   // ALL reads of neigh (s_nt) complete before t overwrites

    // ---- write t = [lrelu(ne)| lrelu(sf)] into s_nt (swizzled) ----
#pragma unroll
    for (int i = 0; i < 4; i++) {
        const int R = r1b + i;
        float4 o;
        o.x = lrelu(acc1[i][0] + s_b1[cn + 0]);
        o.y = lrelu(acc1[i][1] + s_b1[cn + 1]);
        o.z = lrelu(acc1[i][2] + s_b1[cn + 2]);
        o.w = lrelu(acc1[i][3] + s_b1[cn + 3]);
        nt4[R * 32 + ((cn >> 2) ^ swz(R))] = o;
        float4 o2;
        o2.x = lrelu(acc2[i][0] + s_b1[64 + cn + 0]);
        o2.y = lrelu(acc2[i][1] + s_b1[64 + cn + 1]);
        o2.z = lrelu(acc2[i][2] + s_b1[64 + cn + 2]);
        o2.w = lrelu(acc2[i][3] + s_b1[64 + cn + 3]);
        nt4[R * 32 + ((16 + (cn >> 2)) ^ swz(R))] = o2;
    }
    __syncthreads();   // t complete block-wide

    // ---- stage 2: warp owns 32 out cols of all 32 rows; k=128 ----
    float acc[8][4];
#pragma unroll
    for (int r = 0; r < 8; r++) { acc[r][0] = acc[r][1] = acc[r][2] = acc[r][3] = 0.f; }

#pragma unroll 2
    for (int k = 0; k < 64; k += 4) {
        float4 wv0 = *(const float4*)(ne_w2 + (k + 0) * 128 + c0);
        float4 wv1 = *(const float4*)(ne_w2 + (k + 1) * 128 + c0);
        float4 wv2 = *(const float4*)(ne_w2 + (k + 2) * 128 + c0);
        float4 wv3 = *(const float4*)(ne_w2 + (k + 3) * 128 + c0);
#pragma unroll
        for (int i = 0; i < 8; i++) {
            const int R = rg2 * 8 + i;
            float4 a = nt4[R * 32 + ((k >> 2) ^ swz(R))];
            acc[i][0] = fmaf(a.x, wv0.x, acc[i][0]); acc[i][0] = fmaf(a.y, wv1.x, acc[i][0]);
            acc[i][0] = fmaf(a.z, wv2.x, acc[i][0]); acc[i][0] = fmaf(a.w, wv3.x, acc[i][0]);
            acc[i][1] = fmaf(a.x, wv0.y, acc[i][1]); acc[i][1] = fmaf(a.y, wv1.y, acc[i][1]);
            acc[i][1] = fmaf(a.z, wv2.y, acc[i][1]); acc[i][1] = fmaf(a.w, wv3.y, acc[i][1]);
            acc[i][2] = fmaf(a.x, wv0.z, acc[i][2]); acc[i][2] = fmaf(a.y, wv1.z, acc[i][2]);
            acc[i][2] = fmaf(a.z, wv2.z, acc[i][2]); acc[i][2] = fmaf(a.w, wv3.z, acc[i][2]);
            acc[i][3] = fmaf(a.x, wv0.w, acc[i][3]); acc[i][3] = fmaf(a.y, wv1.w, acc[i][3]);
            acc[i][3] = fmaf(a.z, wv2.w, acc[i][3]); acc[i][3] = fmaf(a.w, wv3.w, acc[i][3]);
        }
    }
#pragma unroll 2
    for (int k = 0; k < 64; k += 4) {
        float4 wv0 = *(const float4*)(sf_w2 + (k + 0) * 128 + c0);
        float4 wv1 = *(const float4*)(sf_w2 + (k + 1) * 128 + c0);
        float4 wv2 = *(const float4*)(sf_w2 + (k + 2) * 128 + c0);
        float4 wv3 = *(const float4*)(sf_w2 + (k + 3) * 128 + c0);
#pragma unroll
        for (int i = 0; i < 8; i++) {
            const int R = rg2 * 8 + i;
            float4 a = nt4[R * 32 + ((16 + (k >> 2)) ^ swz(R))];
            acc[i][0] = fmaf(a.x, wv0.x, acc[i][0]); acc[i][0] = fmaf(a.y, wv1.x, acc[i][0]);
            acc[i][0] = fmaf(a.z, wv2.x, acc[i][0]); acc[i][0] = fmaf(a.w, wv3.x, acc[i][0]);
            acc[i][1] = fmaf(a.x, wv0.y, acc[i][1]); acc[i][1] = fmaf(a.y, wv1.y, acc[i][1]);
            acc[i][1] = fmaf(a.z, wv2.y, acc[i][1]); acc[i][1] = fmaf(a.w, wv3.y, acc[i][1]);
            acc[i][2] = fmaf(a.x, wv0.z, acc[i][2]); acc[i][2] = fmaf(a.y, wv1.z, acc[i][2]);
            acc[i][2] = fmaf(a.z, wv2.z, acc[i][2]); acc[i][2] = fmaf(a.w, wv3.z, acc[i][2]);
            acc[i][3] = fmaf(a.x, wv0.w, acc[i][3]); acc[i][3] = fmaf(a.y, wv1.w, acc[i][3]);
            acc[i][3] = fmaf(a.z, wv2.w, acc[i][3]); acc[i][3] = fmaf(a.w, wv3.w, acc[i][3]);
        }
    }

    // ---- epilogue: rows rg2*8+i, cols c0..c0+3 ----
#pragma unroll
    for (int i = 0; i < 8; i++) {
        const int R = rg2 * 8 + i;
        float4 o;
        o.x = acc[i][0] + s_b2[c0 + 0];
        o.y = acc[i][1] + s_b2[c0 + 1];
        o.z = acc[i][2] + s_b2[c0 + 2];
        o.w = acc[i][3] + s_b2[c0 + 3];
        if (DO_RELU) { o.x = relu_(o.x); o.y = relu_(o.y); o.z = relu_(o.z); o.w = relu_(o.w); }
        *(float4*)(g_h + (long long)(lo + row0 + R) * HH + c0) = o;
    }
}

// ---------------------------------------------------------------------------
// Final head (unchanged)
// ---------------------------------------------------------------------------
__global__ void __launch_bounds__(256, 1)
k_final(const float* __restrict__ PO,
        const float* __restrict__ gl_w1, const float* __restrict__ gl_b1,
        const float* __restrict__ gl_w2, const float* __restrict__ gl_b2,
        const float* __restrict__ out_w1, const float* __restrict__ out_b1,
        const float* __restrict__ out_w2, const float* __restrict__ out_b2,
        float* __restrict__ out)
{
    extern __shared__ float smem[];
    float* s_x   = smem;             // 64*256
    float* s_w   = s_x + 16384;      // 64*128
    float* s_t   = s_w + 8192;       // 64*132
    float* s_g1  = s_t + 8448;       // 64*64
    float* s_gb2 = s_g1 + 4096;      // 128
    float* s_ob1 = s_gb2 + 128;      // 128
    float* s_ow2 = s_ob1 + 128;      // 128

    const int tid  = threadIdx.x;
    const int row0 = blockIdx.x * 64;
    const long long gnn0 = (long long)(LL - 1) * PP * HH;

    for (int i = tid; i < 2048; i += 256)
        ((float4*)s_w)[i] = ((const float4*)gl_w2)[i];
    for (int i = tid; i < 128; i += 256) {
        s_gb2[i] = gl_b2[i];
        s_ob1[i] = out_b1[i];
        s_ow2[i] = out_w2[i];
    }
    for (int i = tid; i < 64 * 64; i += 256) {
        int r = i >> 6, c = i & 63;
        s_g1[i] = lrelu(PO[row0 + r] * gl_w1[c] + gl_b1[c]);
    }
    for (int i = tid; i < 2048; i += 256) {
        int r = i >> 5, c4 = i & 31;
        float4 v = *((const float4*)(g_h + gnn0 + (long long)(row0 + r) * HH) + c4);
        *((float4*)(s_x + r * 256) + c4) = v;
    }
    __syncthreads();

    const int w = tid >> 5, l = tid & 31;
    const int r0 = w * 8, c0 = l * 4;

    {
        float acc[8][4];
#pragma unroll
        for (int r = 0; r < 8; r++) { acc[r][0] = acc[r][1] = acc[r][2] = acc[r][3] = 0.f; }
#pragma unroll 4
        for (int k = 0; k < 64; k += 2) {
            float4 w0  = *(const float4*)(s_w + k * 128 + c0);
            float4 w1v = *(const float4*)(s_w + (k + 1) * 128 + c0);
#pragma unroll
            for (int r = 0; r < 8; r++) {
                float2 a = *(const float2*)(s_g1 + (r0 + r) * 64 + k);
                acc[r][0] = fmaf(a.x, w0.x, acc[r][0]); acc[r][0] = fmaf(a.y, w1v.x, acc[r][0]);
                acc[r][1] = fmaf(a.x, w0.y, acc[r][1]); acc[r][1] = fmaf(a.y, w1v.y, acc[r][1]);
                acc[r][2] = fmaf(a.x, w0.z, acc[r][2]); acc[r][2] = fmaf(a.y, w1v.z, acc[r][2]);
                acc[r][3] = fmaf(a.x, w0.w, acc[r][3]); acc[r][3] = fmaf(a.y, w1v.w, acc[r][3]);
            }
        }
#pragma unroll
        for (int r = 0; r < 8; r++) {
            float4 o;
            o.x = acc[r][0] + s_gb2[c0 + 0];
            o.y = acc[r][1] + s_gb2[c0 + 1];
            o.z = acc[r][2] + s_gb2[c0 + 2];
            o.w = acc[r][3] + s_gb2[c0 + 3];
            *(float4*)(s_x + (r0 + r) * 256 + 128 + c0) = o;
        }
    }

    float acc[8][4];
#pragma unroll
    for (int r = 0; r < 8; r++) { acc[r][0] = acc[r][1] = acc[r][2] = acc[r][3] = 0.f; }
    for (int kt = 0; kt < 4; kt++) {
        __syncthreads();
        const float4* src = (const float4*)(out_w1 + kt * 64 * 128);
        for (int i = tid; i < 2048; i += 256) ((float4*)s_w)[i] = src[i];
        __syncthreads();
#pragma unroll 4
        for (int k = 0; k < 64; k += 2) {
            float4 w0  = *(const float4*)(s_w + k * 128 + c0);
            float4 w1v = *(const float4*)(s_w + (k + 1) * 128 + c0);
#pragma unroll
            for (int r = 0; r < 8; r++) {
                float2 a = *(const float2*)(s_x + (r0 + r) * 256 + kt * 64 + k);
                acc[r][0] = fmaf(a.x, w0.x, acc[r][0]); acc[r][0] = fmaf(a.y, w1v.x, acc[r][0]);
                acc[r][1] = fmaf(a.x, w0.y, acc[r][1]); acc[r][1] = fmaf(a.y, w1v.y, acc[r][1]);
                acc[r][2] = fmaf(a.x, w0.z, acc[r][2]); acc[r][2] = fmaf(a.y, w1v.z, acc[r][2]);
                acc[r][3] = fmaf(a.x, w0.w, acc[r][3]); acc[r][3] = fmaf(a.y, w1v.w, acc[r][3]);
            }
        }
    }
#pragma unroll
    for (int r = 0; r < 8; r++) {
        float* t = s_t + (r0 + r) * 132;
        t[c0 + 0] = lrelu(acc[r][0] + s_ob1[c0 + 0]);
        t[c0 + 1] = lrelu(acc[r][1] + s_ob1[c0 + 1]);
        t[c0 + 2] = lrelu(acc[r][2] + s_ob1[c0 + 2]);
        t[c0 + 3] = lrelu(acc[r][3] + s_ob1[c0 + 3]);
    }
    __syncthreads();

    if (tid < 64) {
        float s = out_b2[0];
        const float* t = s_t + tid * 132;
#pragma unroll 8
        for (int k = 0; k < 128; k++) s = fmaf(t[k], s_ow2[k], s);
        out[row0 + tid] = s;
    }
}

// ---------------------------------------------------------------------------
extern "C" void kernel_launch(void* const* d_in, const int* in_sizes, int n_in,
                              void* d_out, int out_size)
{
    // Disambiguate input ordering via in_sizes[3] (pred=3932160 vs pi_w1=64).
    int idx_pred, idx_ispo, wbase;
    if (in_sizes[3] == (LL - 1) * PP * KK) { idx_pred = 3; idx_ispo = 4; wbase = 5; }
    else                                   { idx_pred = 23; idx_ispo = 24; wbase = 3; }
    (void)idx_ispo;

    const float* delay  = (const float*)d_in[0];
    const float* feat   = (const float*)d_in[1];
    const float* PO     = (const float*)d_in[2];
    const int*   pred   = (const int*)d_in[idx_pred];
    const float* pi_w1  = (const float*)d_in[wbase + 0];
    const float* pi_b1  = (const float*)d_in[wbase + 1];
    const float* pi_w2  = (const float*)d_in[wbase + 2];
    const float* pi_b2  = (const float*)d_in[wbase + 3];
    const float* ne_w1  = (const float*)d_in[wbase + 4];
    const float* ne_b1  = (const float*)d_in[wbase + 5];
    const float* ne_w2  = (const float*)d_in[wbase + 6];
    const float* ne_b2  = (const float*)d_in[wbase + 7];
    const float* sf_w1  = (const float*)d_in[wbase + 8];
    const float* sf_b1  = (const float*)d_in[wbase + 9];
    const float* sf_w2  = (const float*)d_in[wbase + 10];
    const float* sf_b2  = (const float*)d_in[wbase + 11];
    const float* gl_w1  = (const float*)d_in[wbase + 12];
    const float* gl_b1  = (const float*)d_in[wbase + 13];
    const float* gl_w2  = (const float*)d_in[wbase + 14];
    const float* gl_b2  = (const float*)d_in[wbase + 15];
    const float* out_w1 = (const float*)d_in[wbase + 16];
    const float* out_b1 = (const float*)d_in[wbase + 17];
    const float* out_w2 = (const float*)d_in[wbase + 18];
    const float* out_b2 = (const float*)d_in[wbase + 19];
    float* out = (float*)d_out;

    const size_t sh_init  = (size_t)(64 * 64 + 64 * 128 + 128) * 4;
    // layer: nt 4096 + ft 1024 + b1 128 + b2 128 + pred 256 = 5632 floats = 22528B
    const size_t sh_layer = (size_t)5632 * 4;
    const size_t sh_final = (size_t)(16384 + 8192 + 8448 + 4096 + 128 + 128 + 128) * 4;

    cudaFuncSetAttribute(k_init,  cudaFuncAttributeMaxDynamicSharedMemorySize, (int)sh_init);
    cudaFuncSetAttribute(k_layer<true>,  cudaFuncAttributeMaxDynamicSharedMemorySize, (int)sh_layer);
    cudaFuncSetAttribute(k_layer<false>, cudaFuncAttributeMaxDynamicSharedMemorySize, (int)sh_layer);
    cudaFuncSetAttribute(k_final, cudaFuncAttributeMaxDynamicSharedMemorySize, (int)sh_final);

    k_init<<<PP / 64, 256, sh_init>>>(delay, pi_w1, pi_b1, pi_w2, pi_b2);
    for (int i = 1; i < LL; i++) {
        const int* pl = pred + (long long)(i - 1) * PP * KK;
        if (i < LL - 1)
            k_layer<true><<<PP / 32, 128, sh_layer>>>(i * PP, pl, feat,
                ne_w1, ne_b1, ne_w2, ne_b2, sf_w1, sf_b1, sf_w2, sf_b2);
        else
            k_layer<false><<<PP / 32, 128, sh_layer>>>(i * PP, pl, feat,
                ne_w1, ne_b1, ne_w2, ne_b2, sf_w1, sf_b1, sf_w2, sf_b2);
    }
    k_final<<<PP / 64, 256, sh_final>>>(PO, gl_w1, gl_b1, gl_w2, gl_b2,
                                        out_w1, out_b1, out_w2, out_b2, out);
}

// round 12
// speedup vs baseline: 1.0200x; 1.0200x over previous
#include <cuda_runtime.h>

#define PP 32768
#define LL 16
#define KK 8
#define HH 128
#define NT_P 33   // s_nt pitch in float4 (128 cols + 4 pad)
#define FT_P 9    // s_ft pitch in float4 (32 cols + 4 pad)

// Full h buffer for all L*P nodes (pred holds GLOBAL indices). 256 MiB static.
__device__ float g_h[(long long)LL * PP * HH];

__device__ __forceinline__ float lrelu(float x) { return x > 0.0f ? x : 0.1f * x; }
__device__ __forceinline__ float relu_(float x) { return x > 0.0f ? x : 0.0f; }

// ---------------------------------------------------------------------------
// h[0:P] = mlp2(delay, pi)   (unchanged)
// ---------------------------------------------------------------------------
__global__ void __launch_bounds__(256, 1)
k_init(const float* __restrict__ delay,
       const float* __restrict__ w1, const float* __restrict__ b1,
       const float* __restrict__ w2, const float* __restrict__ b2)
{
    extern __shared__ float smem[];
    float* s_t1 = smem;            // 64*64
    float* s_w2 = s_t1 + 64 * 64;  // 64*128
    float* s_b2 = s_w2 + 64 * 128; // 128

    const int tid  = threadIdx.x;
    const int row0 = blockIdx.x * 64;

    for (int i = tid; i < (64 * 128) / 4; i += 256)
        ((float4*)s_w2)[i] = ((const float4*)w2)[i];
    for (int i = tid; i < 128; i += 256) s_b2[i] = b2[i];
    for (int i = tid; i < 64 * 64; i += 256) {
        int r = i >> 6, c = i & 63;
        s_t1[i] = lrelu(delay[row0 + r] * w1[c] + b1[c]);
    }
    __syncthreads();

    const int w = tid >> 5, l = tid & 31;
    const int r0 = w * 8, c0 = l * 4;
    float acc[8][4];
#pragma unroll
    for (int r = 0; r < 8; r++)
#pragma unroll
        for (int c = 0; c < 4; c++) acc[r][c] = 0.0f;

#pragma unroll 4
    for (int k = 0; k < 64; k += 2) {
        float4 w0  = *(const float4*)(s_w2 + k * 128 + c0);
        float4 w1v = *(const float4*)(s_w2 + (k + 1) * 128 + c0);
#pragma unroll
        for (int r = 0; r < 8; r++) {
            float2 a = *(const float2*)(s_t1 + (r0 + r) * 64 + k);
            acc[r][0] = fmaf(a.x, w0.x, acc[r][0]); acc[r][0] = fmaf(a.y, w1v.x, acc[r][0]);
            acc[r][1] = fmaf(a.x, w0.y, acc[r][1]); acc[r][1] = fmaf(a.y, w1v.y, acc[r][1]);
            acc[r][2] = fmaf(a.x, w0.z, acc[r][2]); acc[r][2] = fmaf(a.y, w1v.z, acc[r][2]);
            acc[r][3] = fmaf(a.x, w0.w, acc[r][3]); acc[r][3] = fmaf(a.y, w1v.w, acc[r][3]);
        }
    }
#pragma unroll
    for (int r = 0; r < 8; r++) {
        float4 o;
        o.x = acc[r][0] + s_b2[c0 + 0];
        o.y = acc[r][1] + s_b2[c0 + 1];
        o.z = acc[r][2] + s_b2[c0 + 2];
        o.w = acc[r][3] + s_b2[c0 + 3];
        *(float4*)(g_h + (long long)(row0 + r0 + r) * HH + c0) = o;
    }
}

// ---------------------------------------------------------------------------
// Layer i (i=1..15). 128 thr / 32 rows / block, 23.6KB smem, 7 blocks/SM,
// grid 1024 single-wave. Warps split COLUMNS (1 weight wavefront per k).
// Bank conflicts avoided by padded pitch (33/9 float4) + interleaved row
// ownership (concurrent rows differ mod 8) — affine addressing, no XOR.
// ---------------------------------------------------------------------------
template <bool DO_RELU>
__global__ void __launch_bounds__(128, 7)
k_layer(int lo,
        const int*   __restrict__ pred,   // this layer's slice: PP*KK
        const float* __restrict__ feat,
        const float* __restrict__ ne_w1, const float* __restrict__ ne_b1,
        const float* __restrict__ ne_w2, const float* __restrict__ ne_b2,
        const float* __restrict__ sf_w1, const float* __restrict__ sf_b1,
        const float* __restrict__ sf_w2, const float* __restrict__ sf_b2)
{
    extern __shared__ float smem[];
    float* s_nt  = smem;                    // 32*NT_P float4 = 4224 floats
    float* s_ft  = smem + 4224;             // 32*FT_P float4 = 1152 floats
    float* s_b1  = smem + 5376;             // 128
    float* s_b2  = smem + 5504;             // 128
    int*   s_pred = (int*)(smem + 5632);    // 256 ints
    // total 5888 floats = 23552 B
    float4* nt4 = (float4*)s_nt;            // pitch NT_P
    float4* ft4 = (float4*)s_ft;            // pitch FT_P

    const int tid  = threadIdx.x;
    const int row0 = blockIdx.x * 32;

    // ---- preload ft (padded pitch), pred, biases ----
    for (int i = tid; i < 256; i += 128) {
        int r = i >> 3, c4 = i & 7;
        ft4[r * FT_P + c4] =
            *((const float4*)(feat + (long long)(lo + row0 + r) * 32) + c4);
    }
    for (int i = tid; i < 256; i += 128)
        s_pred[i] = pred[(long long)row0 * KK + i];
    if (tid < 128) {
        s_b1[tid] = (tid < 64) ? ne_b1[tid] : sf_b1[tid - 64];
        s_b2[tid] = ne_b2[tid] + sf_b2[tid];
    }
    __syncthreads();

    // ---- gather mean of 8 predecessor rows (padded store) ----
#pragma unroll
    for (int j = 0; j < 8; j++) {
        int task = tid + j * 128;
        int r = task >> 5, c4 = task & 31;
        const int* pr = s_pred + r * 8;
        float x = 0.f, y = 0.f, z = 0.f, ww = 0.f;
#pragma unroll
        for (int k = 0; k < 8; k++) {
            const float4 v = *((const float4*)(g_h + (long long)pr[k] * HH) + c4);
            x += v.x; y += v.y; z += v.z; ww += v.w;
        }
        nt4[r * NT_P + c4] =
            make_float4(x * 0.125f, y * 0.125f, z * 0.125f, ww * 0.125f);
    }
    __syncthreads();

    const int w = tid >> 5, l = tid & 31;
    // stage-1 lane map: rg=l&3, d=(l>>2)&1, cq=l>>3; rows R = 8j + 4d + rg
    const int rg  = l & 3;
    const int d   = (l >> 2) & 1;
    const int cq  = l >> 3;              // 0..3
    const int cn  = w * 16 + cq * 4;     // hidden col base (0..63)
    const int rb1 = 4 * d + rg;          // row base; rows rb1, rb1+8, +16, +24
    // stage-2 lane map: rg2=l&3, cc=l>>2; rows R = 4i + rg2
    const int rg2 = l & 3;
    const int cc  = l >> 2;              // 0..7
    const int c0  = w * 32 + cc * 4;     // out col base (0..127)

    // ---- stage 1, ne path: k=128, 1 weight wavefront per k ----
    float acc1[4][4], acc2[4][4];
#pragma unroll
    for (int i = 0; i < 4; i++)
#pragma unroll
        for (int c = 0; c < 4; c++) { acc1[i][c] = 0.f; acc2[i][c] = 0.f; }

#pragma unroll 4
    for (int k = 0; k < 128; k += 4) {
        float4 wv0 = *(const float4*)(ne_w1 + (k + 0) * 64 + cn);
        float4 wv1 = *(const float4*)(ne_w1 + (k + 1) * 64 + cn);
        float4 wv2 = *(const float4*)(ne_w1 + (k + 2) * 64 + cn);
        float4 wv3 = *(const float4*)(ne_w1 + (k + 3) * 64 + cn);
#pragma unroll
        for (int j = 0; j < 4; j++) {
            float4 a = nt4[(8 * j + rb1) * NT_P + (k >> 2)];
            acc1[j][0] = fmaf(a.x, wv0.x, acc1[j][0]); acc1[j][0] = fmaf(a.y, wv1.x, acc1[j][0]);
            acc1[j][0] = fmaf(a.z, wv2.x, acc1[j][0]); acc1[j][0] = fmaf(a.w, wv3.x, acc1[j][0]);
            acc1[j][1] = fmaf(a.x, wv0.y, acc1[j][1]); acc1[j][1] = fmaf(a.y, wv1.y, acc1[j][1]);
            acc1[j][1] = fmaf(a.z, wv2.y, acc1[j][1]); acc1[j][1] = fmaf(a.w, wv3.y, acc1[j][1]);
            acc1[j][2] = fmaf(a.x, wv0.z, acc1[j][2]); acc1[j][2] = fmaf(a.y, wv1.z, acc1[j][2]);
            acc1[j][2] = fmaf(a.z, wv2.z, acc1[j][2]); acc1[j][2] = fmaf(a.w, wv3.z, acc1[j][2]);
            acc1[j][3] = fmaf(a.x, wv0.w, acc1[j][3]); acc1[j][3] = fmaf(a.y, wv1.w, acc1[j][3]);
            acc1[j][3] = fmaf(a.z, wv2.w, acc1[j][3]); acc1[j][3] = fmaf(a.w, wv3.w, acc1[j][3]);
        }
    }

    // ---- stage 1, sf path: k=32 ----
#pragma unroll 2
    for (int k = 0; k < 32; k += 4) {
        float4 wv0 = *(const float4*)(sf_w1 + (k + 0) * 64 + cn);
        float4 wv1 = *(const float4*)(sf_w1 + (k + 1) * 64 + cn);
        float4 wv2 = *(const float4*)(sf_w1 + (k + 2) * 64 + cn);
        float4 wv3 = *(const float4*)(sf_w1 + (k + 3) * 64 + cn);
#pragma unroll
        for (int j = 0; j < 4; j++) {
            float4 a = ft4[(8 * j + rb1) * FT_P + (k >> 2)];
            acc2[j][0] = fmaf(a.x, wv0.x, acc2[j][0]); acc2[j][0] = fmaf(a.y, wv1.x, acc2[j][0]);
            acc2[j][0] = fmaf(a.z, wv2.x, acc2[j][0]); acc2[j][0] = fmaf(a.w, wv3.x, acc2[j][0]);
            acc2[j][1] = fmaf(a.x, wv0.y, acc2[j][1]); acc2[j][1] = fmaf(a.y, wv1.y, acc2[j][1]);
            acc2[j][1] = fmaf(a.z, wv2.y, acc2[j][1]); acc2[j][1] = fmaf(a.w, wv3.y, acc2[j][1]);
            acc2[j][2] = fmaf(a.x, wv0.z, acc2[j][2]); acc2[j][2] = fmaf(a.y, wv1.z, acc2[j][2]);
            acc2[j][2] = fmaf(a.z, wv2.z, acc2[j][2]); acc2[j][2] = fmaf(a.w, wv3.z, acc2[j][2]);
            acc2[j][3] = fmaf(a.x, wv0.w, acc2[j][3]); acc2[j][3] = fmaf(a.y, wv1.w, acc2[j][3]);
            acc2[j][3] = fmaf(a.z, wv2.w, acc2[j][3]); acc2[j][3] = fmaf(a.w, wv3.w, acc2[j][3]);
        }
    }
    __syncthreads();   // all warps finished reading neigh before t overwrites

    // ---- write t = [lrelu(ne) | lrelu(sf)] back into s_nt ----
#pragma unroll
    for (int j = 0; j < 4; j++) {
        const int R = 8 * j + rb1;
        float4 o;
        o.x = lrelu(acc1[j][0] + s_b1[cn + 0]);
        o.y = lrelu(acc1[j][1] + s_b1[cn + 1]);
        o.z = lrelu(acc1[j][2] + s_b1[cn + 2]);
        o.w = lrelu(acc1[j][3] + s_b1[cn + 3]);
        nt4[R * NT_P + (cn >> 2)] = o;
        float4 o2;
        o2.x = lrelu(acc2[j][0] + s_b1[64 + cn + 0]);
        o2.y = lrelu(acc2[j][1] + s_b1[64 + cn + 1]);
        o2.z = lrelu(acc2[j][2] + s_b1[64 + cn + 2]);
        o2.w = lrelu(acc2[j][3] + s_b1[64 + cn + 3]);
        nt4[R * NT_P + 16 + (cn >> 2)] = o2;
    }
    __syncthreads();   // t complete block-wide

    // ---- stage 2: warp owns 32 out cols of all 32 rows; k=128 ----
    float acc[8][4];
#pragma unroll
    for (int r = 0; r < 8; r++) { acc[r][0] = acc[r][1] = acc[r][2] = acc[r][3] = 0.f; }

#pragma unroll 4
    for (int k = 0; k < 64; k += 4) {
        float4 wv0 = *(const float4*)(ne_w2 + (k + 0) * 128 + c0);
        float4 wv1 = *(const float4*)(ne_w2 + (k + 1) * 128 + c0);
        float4 wv2 = *(const float4*)(ne_w2 + (k + 2) * 128 + c0);
        float4 wv3 = *(const float4*)(ne_w2 + (k + 3) * 128 + c0);
#pragma unroll
        for (int i = 0; i < 8; i++) {
            float4 a = nt4[(4 * i + rg2) * NT_P + (k >> 2)];
            acc[i][0] = fmaf(a.x, wv0.x, acc[i][0]); acc[i][0] = fmaf(a.y, wv1.x, acc[i][0]);
            acc[i][0] = fmaf(a.z, wv2.x, acc[i][0]); acc[i][0] = fmaf(a.w, wv3.x, acc[i][0]);
            acc[i][1] = fmaf(a.x, wv0.y, acc[i][1]); acc[i][1] = fmaf(a.y, wv1.y, acc[i][1]);
            acc[i][1] = fmaf(a.z, wv2.y, acc[i][1]); acc[i][1] = fmaf(a.w, wv3.y, acc[i][1]);
            acc[i][2] = fmaf(a.x, wv0.z, acc[i][2]); acc[i][2] = fmaf(a.y, wv1.z, acc[i][2]);
            acc[i][2] = fmaf(a.z, wv2.z, acc[i][2]); acc[i][2] = fmaf(a.w, wv3.z, acc[i][2]);
            acc[i][3] = fmaf(a.x, wv0.w, acc[i][3]); acc[i][3] = fmaf(a.y, wv1.w, acc[i][3]);
            acc[i][3] = fmaf(a.z, wv2.w, acc[i][3]); acc[i][3] = fmaf(a.w, wv3.w, acc[i][3]);
        }
    }
#pragma unroll 4
    for (int k = 0; k < 64; k += 4) {
        float4 wv0 = *(const float4*)(sf_w2 + (k + 0) * 128 + c0);
        float4 wv1 = *(const float4*)(sf_w2 + (k + 1) * 128 + c0);
        float4 wv2 = *(const float4*)(sf_w2 + (k + 2) * 128 + c0);
        float4 wv3 = *(const float4*)(sf_w2 + (k + 3) * 128 + c0);
#pragma unroll
        for (int i = 0; i < 8; i++) {
            float4 a = nt4[(4 * i + rg2) * NT_P + 16 + (k >> 2)];
            acc[i][0] = fmaf(a.x, wv0.x, acc[i][0]); acc[i][0] = fmaf(a.y, wv1.x, acc[i][0]);
            acc[i][0] = fmaf(a.z, wv2.x, acc[i][0]); acc[i][0] = fmaf(a.w, wv3.x, acc[i][0]);
            acc[i][1] = fmaf(a.x, wv0.y, acc[i][1]); acc[i][1] = fmaf(a.y, wv1.y, acc[i][1]);
            acc[i][1] = fmaf(a.z, wv2.y, acc[i][1]); acc[i][1] = fmaf(a.w, wv3.y, acc[i][1]);
            acc[i][2] = fmaf(a.x, wv0.z, acc[i][2]); acc[i][2] = fmaf(a.y, wv1.z, acc[i][2]);
            acc[i][2] = fmaf(a.z, wv2.z, acc[i][2]); acc[i][2] = fmaf(a.w, wv3.z, acc[i][2]);
            acc[i][3] = fmaf(a.x, wv0.w, acc[i][3]); acc[i][3] = fmaf(a.y, wv1.w, acc[i][3]);
            acc[i][3] = fmaf(a.z, wv2.w, acc[i][3]); acc[i][3] = fmaf(a.w, wv3.w, acc[i][3]);
        }
    }

    // ---- epilogue: rows 4i+rg2, cols c0..c0+3 ----
#pragma unroll
    for (int i = 0; i < 8; i++) {
        const int R = 4 * i + rg2;
        float4 o;
        o.x = acc[i][0] + s_b2[c0 + 0];
        o.y = acc[i][1] + s_b2[c0 + 1];
        o.z = acc[i][2] + s_b2[c0 + 2];
        o.w = acc[i][3] + s_b2[c0 + 3];
        if (DO_RELU) { o.x = relu_(o.x); o.y = relu_(o.y); o.z = relu_(o.z); o.w = relu_(o.w); }
        *(float4*)(g_h + (long long)(lo + row0 + R) * HH + c0) = o;
    }
}

// ---------------------------------------------------------------------------
// Final head (unchanged)
// ---------------------------------------------------------------------------
__global__ void __launch_bounds__(256, 1)
k_final(const float* __restrict__ PO,
        const float* __restrict__ gl_w1, const float* __restrict__ gl_b1,
        const float* __restrict__ gl_w2, const float* __restrict__ gl_b2,
        const float* __restrict__ out_w1, const float* __restrict__ out_b1,
        const float* __restrict__ out_w2, const float* __restrict__ out_b2,
        float* __restrict__ out)
{
    extern __shared__ float smem[];
    float* s_x   = smem;             // 64*256
    float* s_w   = s_x + 16384;      // 64*128
    float* s_t   = s_w + 8192;       // 64*132
    float* s_g1  = s_t + 8448;       // 64*64
    float* s_gb2 = s_g1 + 4096;      // 128
    float* s_ob1 = s_gb2 + 128;      // 128
    float* s_ow2 = s_ob1 + 128;      // 128

    const int tid  = threadIdx.x;
    const int row0 = blockIdx.x * 64;
    const long long gnn0 = (long long)(LL - 1) * PP * HH;

    for (int i = tid; i < 2048; i += 256)
        ((float4*)s_w)[i] = ((const float4*)gl_w2)[i];
    for (int i = tid; i < 128; i += 256) {
        s_gb2[i] = gl_b2[i];
        s_ob1[i] = out_b1[i];
        s_ow2[i] = out_w2[i];
    }
    for (int i = tid; i < 64 * 64; i += 256) {
        int r = i >> 6, c = i & 63;
        s_g1[i] = lrelu(PO[row0 + r] * gl_w1[c] + gl_b1[c]);
    }
    for (int i = tid; i < 2048; i += 256) {
        int r = i >> 5, c4 = i & 31;
        float4 v = *((const float4*)(g_h + gnn0 + (long long)(row0 + r) * HH) + c4);
        *((float4*)(s_x + r * 256) + c4) = v;
    }
    __syncthreads();

    const int w = tid >> 5, l = tid & 31;
    const int r0 = w * 8, c0 = l * 4;

    {
        float acc[8][4];
#pragma unroll
        for (int r = 0; r < 8; r++) { acc[r][0] = acc[r][1] = acc[r][2] = acc[r][3] = 0.f; }
#pragma unroll 4
        for (int k = 0; k < 64; k += 2) {
            float4 w0  = *(const float4*)(s_w + k * 128 + c0);
            float4 w1v = *(const float4*)(s_w + (k + 1) * 128 + c0);
#pragma unroll
            for (int r = 0; r < 8; r++) {
                float2 a = *(const float2*)(s_g1 + (r0 + r) * 64 + k);
                acc[r][0] = fmaf(a.x, w0.x, acc[r][0]); acc[r][0] = fmaf(a.y, w1v.x, acc[r][0]);
                acc[r][1] = fmaf(a.x, w0.y, acc[r][1]); acc[r][1] = fmaf(a.y, w1v.y, acc[r][1]);
                acc[r][2] = fmaf(a.x, w0.z, acc[r][2]); acc[r][2] = fmaf(a.y, w1v.z, acc[r][2]);
                acc[r][3] = fmaf(a.x, w0.w, acc[r][3]); acc[r][3] = fmaf(a.y, w1v.w, acc[r][3]);
            }
        }
#pragma unroll
        for (int r = 0; r < 8; r++) {
            float4 o;
            o.x = acc[r][0] + s_gb2[c0 + 0];
            o.y = acc[r][1] + s_gb2[c0 + 1];
            o.z = acc[r][2] + s_gb2[c0 + 2];
            o.w = acc[r][3] + s_gb2[c0 + 3];
            *(float4*)(s_x + (r0 + r) * 256 + 128 + c0) = o;
        }
    }

    float acc[8][4];
#pragma unroll
    for (int r = 0; r < 8; r++) { acc[r][0] = acc[r][1] = acc[r][2] = acc[r][3] = 0.f; }
    for (int kt = 0; kt < 4; kt++) {
        __syncthreads();
        const float4* src = (const float4*)(out_w1 + kt * 64 * 128);
        for (int i = tid; i < 2048; i += 256) ((float4*)s_w)[i] = src[i];
        __syncthreads();
#pragma unroll 4
        for (int k = 0; k < 64; k += 2) {
            float4 w0  = *(const float4*)(s_w + k * 128 + c0);
            float4 w1v = *(const float4*)(s_w + (k + 1) * 128 + c0);
#pragma unroll
            for (int r = 0; r < 8; r++) {
                float2 a = *(const float2*)(s_x + (r0 + r) * 256 + kt * 64 + k);
                acc[r][0] = fmaf(a.x, w0.x, acc[r][0]); acc[r][0] = fmaf(a.y, w1v.x, acc[r][0]);
                acc[r][1] = fmaf(a.x, w0.y, acc[r][1]); acc[r][1] = fmaf(a.y, w1v.y, acc[r][1]);
                acc[r][2] = fmaf(a.x, w0.z, acc[r][2]); acc[r][2] = fmaf(a.y, w1v.z, acc[r][2]);
                acc[r][3] = fmaf(a.x, w0.w, acc[r][3]); acc[r][3] = fmaf(a.y, w1v.w, acc[r][3]);
            }
        }
    }
#pragma unroll
    for (int r = 0; r < 8; r++) {
        float* t = s_t + (r0 + r) * 132;
        t[c0 + 0] = lrelu(acc[r][0] + s_ob1[c0 + 0]);
        t[c0 + 1] = lrelu(acc[r][1] + s_ob1[c0 + 1]);
        t[c0 + 2] = lrelu(acc[r][2] + s_ob1[c0 + 2]);
        t[c0 + 3] = lrelu(acc[r][3] + s_ob1[c0 + 3]);
    }
    __syncthreads();

    if (tid < 64) {
        float s = out_b2[0];
        const float* t = s_t + tid * 132;
#pragma unroll 8
        for (int k = 0; k < 128; k++) s = fmaf(t[k], s_ow2[k], s);
        out[row0 + tid] = s;
    }
}

// ---------------------------------------------------------------------------
extern "C" void kernel_launch(void* const* d_in, const int* in_sizes, int n_in,
                              void* d_out, int out_size)
{
    // Disambiguate input ordering via in_sizes[3] (pred=3932160 vs pi_w1=64).
    int idx_pred, idx_ispo, wbase;
    if (in_sizes[3] == (LL - 1) * PP * KK) { idx_pred = 3; idx_ispo = 4; wbase = 5; }
    else                                   { idx_pred = 23; idx_ispo = 24; wbase = 3; }
    (void)idx_ispo;

    const float* delay  = (const float*)d_in[0];
    const float* feat   = (const float*)d_in[1];
    const float* PO     = (const float*)d_in[2];
    const int*   pred   = (const int*)d_in[idx_pred];
    const float* pi_w1  = (const float*)d_in[wbase + 0];
    const float* pi_b1  = (const float*)d_in[wbase + 1];
    const float* pi_w2  = (const float*)d_in[wbase + 2];
    const float* pi_b2  = (const float*)d_in[wbase + 3];
    const float* ne_w1  = (const float*)d_in[wbase + 4];
    const float* ne_b1  = (const float*)d_in[wbase + 5];
    const float* ne_w2  = (const float*)d_in[wbase + 6];
    const float* ne_b2  = (const float*)d_in[wbase + 7];
    const float* sf_w1  = (const float*)d_in[wbase + 8];
    const float* sf_b1  = (const float*)d_in[wbase + 9];
    const float* sf_w2  = (const float*)d_in[wbase + 10];
    const float* sf_b2  = (const float*)d_in[wbase + 11];
    const float* gl_w1  = (const float*)d_in[wbase + 12];
    const float* gl_b1  = (const float*)d_in[wbase + 13];
    const float* gl_w2  = (const float*)d_in[wbase + 14];
    const float* gl_b2  = (const float*)d_in[wbase + 15];
    const float* out_w1 = (const float*)d_in[wbase + 16];
    const float* out_b1 = (const float*)d_in[wbase + 17];
    const float* out_w2 = (const float*)d_in[wbase + 18];
    const float* out_b2 = (const float*)d_in[wbase + 19];
    float* out = (float*)d_out;

    const size_t sh_init  = (size_t)(64 * 64 + 64 * 128 + 128) * 4;
    // layer: nt 4224 + ft 1152 + b1 128 + b2 128 + pred 256 = 5888 floats = 23552B
    const size_t sh_layer = (size_t)5888 * 4;
    const size_t sh_final = (size_t)(16384 + 8192 + 8448 + 4096 + 128 + 128 + 128) * 4;

    cudaFuncSetAttribute(k_init,  cudaFuncAttributeMaxDynamicSharedMemorySize, (int)sh_init);
    cudaFuncSetAttribute(k_layer<true>,  cudaFuncAttributeMaxDynamicSharedMemorySize, (int)sh_layer);
    cudaFuncSetAttribute(k_layer<false>, cudaFuncAttributeMaxDynamicSharedMemorySize, (int)sh_layer);
    cudaFuncSetAttribute(k_final, cudaFuncAttributeMaxDynamicSharedMemorySize, (int)sh_final);

    k_init<<<PP / 64, 256, sh_init>>>(delay, pi_w1, pi_b1, pi_w2, pi_b2);
    for (int i = 1; i < LL; i++) {
        const int* pl = pred + (long long)(i - 1) * PP * KK;
        if (i < LL - 1)
            k_layer<true><<<PP / 32, 128, sh_layer>>>(i * PP, pl, feat,
                ne_w1, ne_b1, ne_w2, ne_b2, sf_w1, sf_b1, sf_w2, sf_b2);
        else
            k_layer<false><<<PP / 32, 128, sh_layer>>>(i * PP, pl, feat,
                ne_w1, ne_b1, ne_w2, ne_b2, sf_w1, sf_b1, sf_w2, sf_b2);
    }
    k_final<<<PP / 64, 256, sh_final>>>(PO, gl_w1, gl_b1, gl_w2, gl_b2,
                                        out_w1, out_b1, out_w2, out_b2, out);
}

// round 13
// speedup vs baseline: 1.0989x; 1.0774x over previous
#include <cuda_runtime.h>

#define PP 32768
#define LL 16
#define KK 8
#define HH 128

// Full h buffer for all L*P nodes (pred holds GLOBAL indices). 256 MiB static.
__device__ float g_h[(long long)LL * PP * HH];

__device__ __forceinline__ float lrelu(float x) { return x > 0.0f ? x : 0.1f * x; }
__device__ __forceinline__ float relu_(float x) { return x > 0.0f ? x : 0.0f; }

// ---------------------------------------------------------------------------
// h[0:P] = mlp2(delay, pi)   (unchanged)
// ---------------------------------------------------------------------------
__global__ void __launch_bounds__(256, 1)
k_init(const float* __restrict__ delay,
       const float* __restrict__ w1, const float* __restrict__ b1,
       const float* __restrict__ w2, const float* __restrict__ b2)
{
    extern __shared__ float smem[];
    float* s_t1 = smem;            // 64*64
    float* s_w2 = s_t1 + 64 * 64;  // 64*128
    float* s_b2 = s_w2 + 64 * 128; // 128

    const int tid  = threadIdx.x;
    const int row0 = blockIdx.x * 64;

    for (int i = tid; i < (64 * 128) / 4; i += 256)
        ((float4*)s_w2)[i] = ((const float4*)w2)[i];
    for (int i = tid; i < 128; i += 256) s_b2[i] = b2[i];
    for (int i = tid; i < 64 * 64; i += 256) {
        int r = i >> 6, c = i & 63;
        s_t1[i] = lrelu(delay[row0 + r] * w1[c] + b1[c]);
    }
    __syncthreads();

    const int w = tid >> 5, l = tid & 31;
    const int r0 = w * 8, c0 = l * 4;
    float acc[8][4];
#pragma unroll
    for (int r = 0; r < 8; r++)
#pragma unroll
        for (int c = 0; c < 4; c++) acc[r][c] = 0.0f;

#pragma unroll 4
    for (int k = 0; k < 64; k += 2) {
        float4 w0  = *(const float4*)(s_w2 + k * 128 + c0);
        float4 w1v = *(const float4*)(s_w2 + (k + 1) * 128 + c0);
#pragma unroll
        for (int r = 0; r < 8; r++) {
            float2 a = *(const float2*)(s_t1 + (r0 + r) * 64 + k);
            acc[r][0] = fmaf(a.x, w0.x, acc[r][0]); acc[r][0] = fmaf(a.y, w1v.x, acc[r][0]);
            acc[r][1] = fmaf(a.x, w0.y, acc[r][1]); acc[r][1] = fmaf(a.y, w1v.y, acc[r][1]);
            acc[r][2] = fmaf(a.x, w0.z, acc[r][2]); acc[r][2] = fmaf(a.y, w1v.z, acc[r][2]);
            acc[r][3] = fmaf(a.x, w0.w, acc[r][3]); acc[r][3] = fmaf(a.y, w1v.w, acc[r][3]);
        }
    }
#pragma unroll
    for (int r = 0; r < 8; r++) {
        float4 o;
        o.x = acc[r][0] + s_b2[c0 + 0];
        o.y = acc[r][1] + s_b2[c0 + 1];
        o.z = acc[r][2] + s_b2[c0 + 2];
        o.w = acc[r][3] + s_b2[c0 + 3];
        *(float4*)(g_h + (long long)(row0 + r0 + r) * HH + c0) = o;
    }
}

// ---------------------------------------------------------------------------
// Layer i (i=1..15). 128 thr / 32 rows / block, 22.5KB smem, 7 blocks/SM,
// grid 1024 single-wave. FULLY WARP-LOCAL after the bias preload:
// warp w gathers / stage-1s / stage-2s its own 8 rows; only __syncwarp
// after the one initial __syncthreads (biases). R7 layouts (broadcast
// activation LDS, direct-global weight LDG) proven best.
// ---------------------------------------------------------------------------
template <bool DO_RELU>
__global__ void __launch_bounds__(128, 7)
k_layer(int lo,
        const int*   __restrict__ pred,   // this layer's slice: PP*KK
        const float* __restrict__ feat,
        const float* __restrict__ ne_w1, const float* __restrict__ ne_b1,
        const float* __restrict__ ne_w2, const float* __restrict__ ne_b2,
        const float* __restrict__ sf_w1, const float* __restrict__ sf_b1,
        const float* __restrict__ sf_w2, const float* __restrict__ sf_b2)
{
    extern __shared__ float smem[];
    float* s_nt  = smem;            // 32*128 = 4096 floats (neigh, then t)
    float* s_ft  = smem + 4096;     // 32*32 = 1024
    float* s_b1  = smem + 5120;     // 128
    float* s_b2  = smem + 5248;     // 128
    int*   s_pred = (int*)(smem + 5376);  // 256 ints (64 per warp)
    // total 5632 floats = 22528 B

    const int tid  = threadIdx.x;
    const int w    = tid >> 5, l = tid & 31;
    const int row0 = blockIdx.x * 32;
    const int r0   = w * 8;

    // ---- block-shared biases: the ONLY __syncthreads in this kernel ----
    s_b1[tid] = (tid < 64) ? ne_b1[tid] : sf_b1[tid - 64];
    s_b2[tid] = ne_b2[tid] + sf_b2[tid];
    __syncthreads();

    // ---- per-warp: own pred indices (64) + own feat rows (8 x 32) ----
    s_pred[w * 64 + l]      = pred[(long long)(row0 + r0) * KK + l];
    s_pred[w * 64 + 32 + l] = pred[(long long)(row0 + r0) * KK + 32 + l];
    for (int i = l; i < 64; i += 32) {
        int r = i >> 3, c4 = i & 7;
        ((float4*)(s_ft + (r0 + r) * 32))[c4] =
            *((const float4*)(feat + (long long)(lo + row0 + r0 + r) * 32) + c4);
    }
    __syncwarp();

    // ---- gather mean of 8 predecessors for OWN 8 rows (warp-local) ----
    float4* nt4 = (float4*)s_nt;    // pitch 32 float4 per row
    const int* pw = s_pred + w * 64;
#pragma unroll
    for (int r = 0; r < 8; r++) {
        const int* pr = pw + r * 8;
        float x = 0.f, y = 0.f, z = 0.f, s = 0.f;
#pragma unroll
        for (int k = 0; k < 8; k++) {
            const float4 v = *((const float4*)(g_h + (long long)pr[k] * HH) + l);
            x += v.x; y += v.y; z += v.z; s += v.w;
        }
        nt4[(r0 + r) * 32 + l] =
            make_float4(x * 0.125f, y * 0.125f, z * 0.125f, s * 0.125f);
    }
    __syncwarp();

    // stage-1 mapping: half-warp = 4 rows, (l&15)*4 = 4 cols (R7-proven)
    const int r1 = r0 + (l >> 4) * 4;
    const int cg = (l & 15) * 4;

    // ---- stage 1, ne path: k=128, weights streamed from global ----
    float accA[4][4];
#pragma unroll
    for (int i = 0; i < 4; i++)
#pragma unroll
        for (int c = 0; c < 4; c++) accA[i][c] = 0.f;

#pragma unroll 2
    for (int k = 0; k < 128; k += 4) {
        float4 wv0 = *(const float4*)(ne_w1 + (k + 0) * 64 + cg);
        float4 wv1 = *(const float4*)(ne_w1 + (k + 1) * 64 + cg);
        float4 wv2 = *(const float4*)(ne_w1 + (k + 2) * 64 + cg);
        float4 wv3 = *(const float4*)(ne_w1 + (k + 3) * 64 + cg);
#pragma unroll
        for (int i = 0; i < 4; i++) {
            float4 a = *(const float4*)(s_nt + (r1 + i) * 128 + k);
            accA[i][0] = fmaf(a.x, wv0.x, accA[i][0]); accA[i][0] = fmaf(a.y, wv1.x, accA[i][0]);
            accA[i][0] = fmaf(a.z, wv2.x, accA[i][0]); accA[i][0] = fmaf(a.w, wv3.x, accA[i][0]);
            accA[i][1] = fmaf(a.x, wv0.y, accA[i][1]); accA[i][1] = fmaf(a.y, wv1.y, accA[i][1]);
            accA[i][1] = fmaf(a.z, wv2.y, accA[i][1]); accA[i][1] = fmaf(a.w, wv3.y, accA[i][1]);
            accA[i][2] = fmaf(a.x, wv0.z, accA[i][2]); accA[i][2] = fmaf(a.y, wv1.z, accA[i][2]);
            accA[i][2] = fmaf(a.z, wv2.z, accA[i][2]); accA[i][2] = fmaf(a.w, wv3.z, accA[i][2]);
            accA[i][3] = fmaf(a.x, wv0.w, accA[i][3]); accA[i][3] = fmaf(a.y, wv1.w, accA[i][3]);
            accA[i][3] = fmaf(a.z, wv2.w, accA[i][3]); accA[i][3] = fmaf(a.w, wv3.w, accA[i][3]);
        }
    }
    __syncwarp();   // all lanes done reading neigh before t_ne overwrites

    // t_ne -> s_nt cols [cg, cg+4) of own 4 rows
#pragma unroll
    for (int i = 0; i < 4; i++) {
        float4 o;
        o.x = lrelu(accA[i][0] + s_b1[cg + 0]);
        o.y = lrelu(accA[i][1] + s_b1[cg + 1]);
        o.z = lrelu(accA[i][2] + s_b1[cg + 2]);
        o.w = lrelu(accA[i][3] + s_b1[cg + 3]);
        *(float4*)(s_nt + (r1 + i) * 128 + cg) = o;
    }

    // ---- stage 1, sf path: k=32 over s_ft (weights from global) ----
    float accB[4][4];
#pragma unroll
    for (int i = 0; i < 4; i++)
#pragma unroll
        for (int c = 0; c < 4; c++) accB[i][c] = 0.f;

#pragma unroll 2
    for (int k = 0; k < 32; k += 4) {
        float4 wv0 = *(const float4*)(sf_w1 + (k + 0) * 64 + cg);
        float4 wv1 = *(const float4*)(sf_w1 + (k + 1) * 64 + cg);
        float4 wv2 = *(const float4*)(sf_w1 + (k + 2) * 64 + cg);
        float4 wv3 = *(const float4*)(sf_w1 + (k + 3) * 64 + cg);
#pragma unroll
        for (int i = 0; i < 4; i++) {
            float4 a = *(const float4*)(s_ft + (r1 + i) * 32 + k);
            accB[i][0] = fmaf(a.x, wv0.x, accB[i][0]); accB[i][0] = fmaf(a.y, wv1.x, accB[i][0]);
            accB[i][0] = fmaf(a.z, wv2.x, accB[i][0]); accB[i][0] = fmaf(a.w, wv3.x, accB[i][0]);
            accB[i][1] = fmaf(a.x, wv0.y, accB[i][1]); accB[i][1] = fmaf(a.y, wv1.y, accB[i][1]);
            accB[i][1] = fmaf(a.z, wv2.y, accB[i][1]); accB[i][1] = fmaf(a.w, wv3.y, accB[i][1]);
            accB[i][2] = fmaf(a.x, wv0.z, accB[i][2]); accB[i][2] = fmaf(a.y, wv1.z, accB[i][2]);
            accB[i][2] = fmaf(a.z, wv2.z, accB[i][2]); accB[i][2] = fmaf(a.w, wv3.z, accB[i][2]);
            accB[i][3] = fmaf(a.x, wv0.w, accB[i][3]); accB[i][3] = fmaf(a.y, wv1.w, accB[i][3]);
            accB[i][3] = fmaf(a.z, wv2.w, accB[i][3]); accB[i][3] = fmaf(a.w, wv3.w, accB[i][3]);
        }
    }
    // t_sf -> s_nt cols [64+cg, 64+cg+4) of own 4 rows
#pragma unroll
    for (int i = 0; i < 4; i++) {
        float4 o;
        o.x = lrelu(accB[i][0] + s_b1[64 + cg + 0]);
        o.y = lrelu(accB[i][1] + s_b1[64 + cg + 1]);
        o.z = lrelu(accB[i][2] + s_b1[64 + cg + 2]);
        o.w = lrelu(accB[i][3] + s_b1[64 + cg + 3]);
        *(float4*)(s_nt + (r1 + i) * 128 + 64 + cg) = o;
    }
    __syncwarp();   // t complete for this warp's 8 rows

    // ---- stage 2: k=128 (ne_w2 for t cols 0..63, sf_w2 for 64..127) ----
    const int c0 = l * 4;
    float acc[8][4];
#pragma unroll
    for (int r = 0; r < 8; r++) { acc[r][0] = acc[r][1] = acc[r][2] = acc[r][3] = 0.f; }

#pragma unroll 2
    for (int k = 0; k < 64; k += 4) {
        float4 wv0 = *(const float4*)(ne_w2 + (k + 0) * 128 + c0);
        float4 wv1 = *(const float4*)(ne_w2 + (k + 1) * 128 + c0);
        float4 wv2 = *(const float4*)(ne_w2 + (k + 2) * 128 + c0);
        float4 wv3 = *(const float4*)(ne_w2 + (k + 3) * 128 + c0);
#pragma unroll
        for (int r = 0; r < 8; r++) {
            float4 a = *(const float4*)(s_nt + (r0 + r) * 128 + k);
            acc[r][0] = fmaf(a.x, wv0.x, acc[r][0]); acc[r][0] = fmaf(a.y, wv1.x, acc[r][0]);
            acc[r][0] = fmaf(a.z, wv2.x, acc[r][0]); acc[r][0] = fmaf(a.w, wv3.x, acc[r][0]);
            acc[r][1] = fmaf(a.x, wv0.y, acc[r][1]); acc[r][1] = fmaf(a.y, wv1.y, acc[r][1]);
            acc[r][1] = fmaf(a.z, wv2.y, acc[r][1]); acc[r][1] = fmaf(a.w, wv3.y, acc[r][1]);
            acc[r][2] = fmaf(a.x, wv0.z, acc[r][2]); acc[r][2] = fmaf(a.y, wv1.z, acc[r][2]);
            acc[r][2] = fmaf(a.z, wv2.z, acc[r][2]); acc[r][2] = fmaf(a.w, wv3.z, acc[r][2]);
            acc[r][3] = fmaf(a.x, wv0.w, acc[r][3]); acc[r][3] = fmaf(a.y, wv1.w, acc[r][3]);
            acc[r][3] = fmaf(a.z, wv2.w, acc[r][3]); acc[r][3] = fmaf(a.w, wv3.w, acc[r][3]);
        }
    }
#pragma unroll 2
    for (int k = 0; k < 64; k += 4) {
        float4 wv0 = *(const float4*)(sf_w2 + (k + 0) * 128 + c0);
        float4 wv1 = *(const float4*)(sf_w2 + (k + 1) * 128 + c0);
        float4 wv2 = *(const float4*)(sf_w2 + (k + 2) * 128 + c0);
        float4 wv3 = *(const float4*)(sf_w2 + (k + 3) * 128 + c0);
#pragma unroll
        for (int r = 0; r < 8; r++) {
            float4 a = *(const float4*)(s_nt + (r0 + r) * 128 + 64 + k);
            acc[r][0] = fmaf(a.x, wv0.x, acc[r][0]); acc[r][0] = fmaf(a.y, wv1.x, acc[r][0]);
            acc[r][0] = fmaf(a.z, wv2.x, acc[r][0]); acc[r][0] = fmaf(a.w, wv3.x, acc[r][0]);
            acc[r][1] = fmaf(a.x, wv0.y, acc[r][1]); acc[r][1] = fmaf(a.y, wv1.y, acc[r][1]);
            acc[r][1] = fmaf(a.z, wv2.y, acc[r][1]); acc[r][1] = fmaf(a.w, wv3.y, acc[r][1]);
            acc[r][2] = fmaf(a.x, wv0.z, acc[r][2]); acc[r][2] = fmaf(a.y, wv1.z, acc[r][2]);
            acc[r][2] = fmaf(a.z, wv2.z, acc[r][2]); acc[r][2] = fmaf(a.w, wv3.z, acc[r][2]);
            acc[r][3] = fmaf(a.x, wv0.w, acc[r][3]); acc[r][3] = fmaf(a.y, wv1.w, acc[r][3]);
            acc[r][3] = fmaf(a.z, wv2.w, acc[r][3]); acc[r][3] = fmaf(a.w, wv3.w, acc[r][3]);
        }
    }

    // ---- epilogue ----
#pragma unroll
    for (int r = 0; r < 8; r++) {
        float4 o;
        o.x = acc[r][0] + s_b2[c0 + 0];
        o.y = acc[r][1] + s_b2[c0 + 1];
        o.z = acc[r][2] + s_b2[c0 + 2];
        o.w = acc[r][3] + s_b2[c0 + 3];
        if (DO_RELU) { o.x = relu_(o.x); o.y = relu_(o.y); o.z = relu_(o.z); o.w = relu_(o.w); }
        *(float4*)(g_h + (long long)(lo + row0 + r0 + r) * HH + c0) = o;
    }
}

// ---------------------------------------------------------------------------
// Final head (unchanged)
// ---------------------------------------------------------------------------
__global__ void __launch_bounds__(256, 1)
k_final(const float* __restrict__ PO,
        const float* __restrict__ gl_w1, const float* __restrict__ gl_b1,
        const float* __restrict__ gl_w2, const float* __restrict__ gl_b2,
        const float* __restrict__ out_w1, const float* __restrict__ out_b1,
        const float* __restrict__ out_w2, const float* __restrict__ out_b2,
        float* __restrict__ out)
{
    extern __shared__ float smem[];
    float* s_x   = smem;             // 64*256
    float* s_w   = s_x + 16384;      // 64*128
    float* s_t   = s_w + 8192;       // 64*132
    float* s_g1  = s_t + 8448;       // 64*64
    float* s_gb2 = s_g1 + 4096;      // 128
    float* s_ob1 = s_gb2 + 128;      // 128
    float* s_ow2 = s_ob1 + 128;      // 128

    const int tid  = threadIdx.x;
    const int row0 = blockIdx.x * 64;
    const long long gnn0 = (long long)(LL - 1) * PP * HH;

    for (int i = tid; i < 2048; i += 256)
        ((float4*)s_w)[i] = ((const float4*)gl_w2)[i];
    for (int i = tid; i < 128; i += 256) {
        s_gb2[i] = gl_b2[i];
        s_ob1[i] = out_b1[i];
        s_ow2[i] = out_w2[i];
    }
    for (int i = tid; i < 64 * 64; i += 256) {
        int r = i >> 6, c = i & 63;
        s_g1[i] = lrelu(PO[row0 + r] * gl_w1[c] + gl_b1[c]);
    }
    for (int i = tid; i < 2048; i += 256) {
        int r = i >> 5, c4 = i & 31;
        float4 v = *((const float4*)(g_h + gnn0 + (long long)(row0 + r) * HH) + c4);
        *((float4*)(s_x + r * 256) + c4) = v;
    }
    __syncthreads();

    const int w = tid >> 5, l = tid & 31;
    const int r0 = w * 8, c0 = l * 4;

    {
        float acc[8][4];
#pragma unroll
        for (int r = 0; r < 8; r++) { acc[r][0] = acc[r][1] = acc[r][2] = acc[r][3] = 0.f; }
#pragma unroll 4
        for (int k = 0; k < 64; k += 2) {
            float4 w0  = *(const float4*)(s_w + k * 128 + c0);
            float4 w1v = *(const float4*)(s_w + (k + 1) * 128 + c0);
#pragma unroll
            for (int r = 0; r < 8; r++) {
                float2 a = *(const float2*)(s_g1 + (r0 + r) * 64 + k);
                acc[r][0] = fmaf(a.x, w0.x, acc[r][0]); acc[r][0] = fmaf(a.y, w1v.x, acc[r][0]);
                acc[r][1] = fmaf(a.x, w0.y, acc[r][1]); acc[r][1] = fmaf(a.y, w1v.y, acc[r][1]);
                acc[r][2] = fmaf(a.x, w0.z, acc[r][2]); acc[r][2] = fmaf(a.y, w1v.z, acc[r][2]);
                acc[r][3] = fmaf(a.x, w0.w, acc[r][3]); acc[r][3] = fmaf(a.y, w1v.w, acc[r][3]);
            }
        }
#pragma unroll
        for (int r = 0; r < 8; r++) {
            float4 o;
            o.x = acc[r][0] + s_gb2[c0 + 0];
            o.y = acc[r][1] + s_gb2[c0 + 1];
            o.z = acc[r][2] + s_gb2[c0 + 2];
            o.w = acc[r][3] + s_gb2[c0 + 3];
            *(float4*)(s_x + (r0 + r) * 256 + 128 + c0) = o;
        }
    }

    float acc[8][4];
#pragma unroll
    for (int r = 0; r < 8; r++) { acc[r][0] = acc[r][1] = acc[r][2] = acc[r][3] = 0.f; }
    for (int kt = 0; kt < 4; kt++) {
        __syncthreads();
        const float4* src = (const float4*)(out_w1 + kt * 64 * 128);
        for (int i = tid; i < 2048; i += 256) ((float4*)s_w)[i] = src[i];
        __syncthreads();
#pragma unroll 4
        for (int k = 0; k < 64; k += 2) {
            float4 w0  = *(const float4*)(s_w + k * 128 + c0);
            float4 w1v = *(const float4*)(s_w + (k + 1) * 128 + c0);
#pragma unroll
            for (int r = 0; r < 8; r++) {
                float2 a = *(const float2*)(s_x + (r0 + r) * 256 + kt * 64 + k);
                acc[r][0] = fmaf(a.x, w0.x, acc[r][0]); acc[r][0] = fmaf(a.y, w1v.x, acc[r][0]);
                acc[r][1] = fmaf(a.x, w0.y, acc[r][1]); acc[r][1] = fmaf(a.y, w1v.y, acc[r][1]);
                acc[r][2] = fmaf(a.x, w0.z, acc[r][2]); acc[r][2] = fmaf(a.y, w1v.z, acc[r][2]);
                acc[r][3] = fmaf(a.x, w0.w, acc[r][3]); acc[r][3] = fmaf(a.y, w1v.w, acc[r][3]);
            }
        }
    }
#pragma unroll
    for (int r = 0; r < 8; r++) {
        float* t = s_t + (r0 + r) * 132;
        t[c0 + 0] = lrelu(acc[r][0] + s_ob1[c0 + 0]);
        t[c0 + 1] = lrelu(acc[r][1] + s_ob1[c0 + 1]);
        t[c0 + 2] = lrelu(acc[r][2] + s_ob1[c0 + 2]);
        t[c0 + 3] = lrelu(acc[r][3] + s_ob1[c0 + 3]);
    }
    __syncthreads();

    if (tid < 64) {
        float s = out_b2[0];
        const float* t = s_t + tid * 132;
#pragma unroll 8
        for (int k = 0; k < 128; k++) s = fmaf(t[k], s_ow2[k], s);
        out[row0 + tid] = s;
    }
}

// ---------------------------------------------------------------------------
extern "C" void kernel_launch(void* const* d_in, const int* in_sizes, int n_in,
                              void* d_out, int out_size)
{
    // Disambiguate input ordering via in_sizes[3] (pred=3932160 vs pi_w1=64).
    int idx_pred, idx_ispo, wbase;
    if (in_sizes[3] == (LL - 1) * PP * KK) { idx_pred = 3; idx_ispo = 4; wbase = 5; }
    else                                   { idx_pred = 23; idx_ispo = 24; wbase = 3; }
    (void)idx_ispo;

    const float* delay  = (const float*)d_in[0];
    const float* feat   = (const float*)d_in[1];
    const float* PO     = (const float*)d_in[2];
    const int*   pred   = (const int*)d_in[idx_pred];
    const float* pi_w1  = (const float*)d_in[wbase + 0];
    const float* pi_b1  = (const float*)d_in[wbase + 1];
    const float* pi_w2  = (const float*)d_in[wbase + 2];
    const float* pi_b2  = (const float*)d_in[wbase + 3];
    const float* ne_w1  = (const float*)d_in[wbase + 4];
    const float* ne_b1  = (const float*)d_in[wbase + 5];
    const float* ne_w2  = (const float*)d_in[wbase + 6];
    const float* ne_b2  = (const float*)d_in[wbase + 7];
    const float* sf_w1  = (const float*)d_in[wbase + 8];
    const float* sf_b1  = (const float*)d_in[wbase + 9];
    const float* sf_w2  = (const float*)d_in[wbase + 10];
    const float* sf_b2  = (const float*)d_in[wbase + 11];
    const float* gl_w1  = (const float*)d_in[wbase + 12];
    const float* gl_b1  = (const float*)d_in[wbase + 13];
    const float* gl_w2  = (const float*)d_in[wbase + 14];
    const float* gl_b2  = (const float*)d_in[wbase + 15];
    const float* out_w1 = (const float*)d_in[wbase + 16];
    const float* out_b1 = (const float*)d_in[wbase + 17];
    const float* out_w2 = (const float*)d_in[wbase + 18];
    const float* out_b2 = (const float*)d_in[wbase + 19];
    float* out = (float*)d_out;

    const size_t sh_init  = (size_t)(64 * 64 + 64 * 128 + 128) * 4;
    // layer: nt 4096 + ft 1024 + b1 128 + b2 128 + pred 256 = 5632 floats = 22528B
    const size_t sh_layer = (size_t)5632 * 4;
    const size_t sh_final = (size_t)(16384 + 8192 + 8448 + 4096 + 128 + 128 + 128) * 4;

    cudaFuncSetAttribute(k_init,  cudaFuncAttributeMaxDynamicSharedMemorySize, (int)sh_init);
    cudaFuncSetAttribute(k_layer<true>,  cudaFuncAttributeMaxDynamicSharedMemorySize, (int)sh_layer);
    cudaFuncSetAttribute(k_layer<false>, cudaFuncAttributeMaxDynamicSharedMemorySize, (int)sh_layer);
    cudaFuncSetAttribute(k_final, cudaFuncAttributeMaxDynamicSharedMemorySize, (int)sh_final);

    k_init<<<PP / 64, 256, sh_init>>>(delay, pi_w1, pi_b1, pi_w2, pi_b2);
    for (int i = 1; i < LL; i++) {
        const int* pl = pred + (long long)(i - 1) * PP * KK;
        if (i < LL - 1)
            k_layer<true><<<PP / 32, 128, sh_layer>>>(i * PP, pl, feat,
                ne_w1, ne_b1, ne_w2, ne_b2, sf_w1, sf_b1, sf_w2, sf_b2);
        else
            k_layer<false><<<PP / 32, 128, sh_layer>>>(i * PP, pl, feat,
                ne_w1, ne_b1, ne_w2, ne_b2, sf_w1, sf_b1, sf_w2, sf_b2);
    }
    k_final<<<PP / 64, 256, sh_final>>>(PO, gl_w1, gl_b1, gl_w2, gl_b2,
                                        out_w1, out_b1, out_w2, out_b2, out);
}

// round 14
// speedup vs baseline: 1.1988x; 1.0909x over previous
#include <cuda_runtime.h>

#define PP 32768
#define LL 16
#define KK 8
#define HH 128
#define YW 64   // width of the pre-projected gather payload y = h @ ne_w1

// h only needed for layer 15 (final head); y carries layers 0..14.
__device__ float g_h[(long long)LL * PP * HH];   // 256 MiB
__device__ float g_y[(long long)LL * PP * YW];   // 128 MiB

__device__ __forceinline__ float lrelu(float x) { return x > 0.0f ? x : 0.1f * x; }
__device__ __forceinline__ float relu_(float x) { return x > 0.0f ? x : 0.0f; }

// ---------------------------------------------------------------------------
// k_init: h0 = mlp2(delay, pi) (kept in smem), then y0 = h0 @ ne_w1 -> g_y.
// ---------------------------------------------------------------------------
__global__ void __launch_bounds__(256, 1)
k_init(const float* __restrict__ delay,
       const float* __restrict__ w1, const float* __restrict__ b1,
       const float* __restrict__ w2, const float* __restrict__ b2,
       const float* __restrict__ ne_w1)
{
    extern __shared__ float smem[];
    float* s_t1 = smem;            // 64*64  = 4096
    float* s_w2 = smem + 4096;     // 64*128 = 8192
    float* s_b2 = smem + 12288;    // 128
    float* s_h  = smem + 12416;    // 64*128 = 8192

    const int tid  = threadIdx.x;
    const int row0 = blockIdx.x * 64;

    for (int i = tid; i < 2048; i += 256)
        ((float4*)s_w2)[i] = ((const float4*)w2)[i];
    for (int i = tid; i < 128; i += 256) s_b2[i] = b2[i];
    for (int i = tid; i < 64 * 64; i += 256) {
        int r = i >> 6, c = i & 63;
        s_t1[i] = lrelu(delay[row0 + r] * w1[c] + b1[c]);
    }
    __syncthreads();

    const int w = tid >> 5, l = tid & 31;
    const int r0 = w * 8, c0 = l * 4;
    float acc[8][4];
#pragma unroll
    for (int r = 0; r < 8; r++)
#pragma unroll
        for (int c = 0; c < 4; c++) acc[r][c] = 0.0f;

#pragma unroll 4
    for (int k = 0; k < 64; k += 2) {
        float4 w0  = *(const float4*)(s_w2 + k * 128 + c0);
        float4 w1v = *(const float4*)(s_w2 + (k + 1) * 128 + c0);
#pragma unroll
        for (int r = 0; r < 8; r++) {
            float2 a = *(const float2*)(s_t1 + (r0 + r) * 64 + k);
            acc[r][0] = fmaf(a.x, w0.x, acc[r][0]); acc[r][0] = fmaf(a.y, w1v.x, acc[r][0]);
            acc[r][1] = fmaf(a.x, w0.y, acc[r][1]); acc[r][1] = fmaf(a.y, w1v.y, acc[r][1]);
            acc[r][2] = fmaf(a.x, w0.z, acc[r][2]); acc[r][2] = fmaf(a.y, w1v.z, acc[r][2]);
            acc[r][3] = fmaf(a.x, w0.w, acc[r][3]); acc[r][3] = fmaf(a.y, w1v.w, acc[r][3]);
        }
    }
#pragma unroll
    for (int r = 0; r < 8; r++) {
        float4 o;
        o.x = acc[r][0] + s_b2[c0 + 0];
        o.y = acc[r][1] + s_b2[c0 + 1];
        o.z = acc[r][2] + s_b2[c0 + 2];
        o.w = acc[r][3] + s_b2[c0 + 3];
        *(float4*)(s_h + (r0 + r) * 128 + c0) = o;   // h0 stays in smem
    }
    __syncthreads();

    // y0 = h0 @ ne_w1 (64 cols); half-warp map: 4 rows x 4 cols per lane
    const int r1 = r0 + (l >> 4) * 4;
    const int cg = (l & 15) * 4;
    float accY[4][4];
#pragma unroll
    for (int i = 0; i < 4; i++)
#pragma unroll
        for (int c = 0; c < 4; c++) accY[i][c] = 0.f;
#pragma unroll 2
    for (int k = 0; k < 128; k += 4) {
        float4 wv0 = *(const float4*)(ne_w1 + (k + 0) * 64 + cg);
        float4 wv1 = *(const float4*)(ne_w1 + (k + 1) * 64 + cg);
        float4 wv2 = *(const float4*)(ne_w1 + (k + 2) * 64 + cg);
        float4 wv3 = *(const float4*)(ne_w1 + (k + 3) * 64 + cg);
#pragma unroll
        for (int i = 0; i < 4; i++) {
            float4 a = *(const float4*)(s_h + (r1 + i) * 128 + k);
            accY[i][0] = fmaf(a.x, wv0.x, accY[i][0]); accY[i][0] = fmaf(a.y, wv1.x, accY[i][0]);
            accY[i][0] = fmaf(a.z, wv2.x, accY[i][0]); accY[i][0] = fmaf(a.w, wv3.x, accY[i][0]);
            accY[i][1] = fmaf(a.x, wv0.y, accY[i][1]); accY[i][1] = fmaf(a.y, wv1.y, accY[i][1]);
            accY[i][1] = fmaf(a.z, wv2.y, accY[i][1]); accY[i][1] = fmaf(a.w, wv3.y, accY[i][1]);
            accY[i][2] = fmaf(a.x, wv0.z, accY[i][2]); accY[i][2] = fmaf(a.y, wv1.z, accY[i][2]);
            accY[i][2] = fmaf(a.z, wv2.z, accY[i][2]); accY[i][2] = fmaf(a.w, wv3.z, accY[i][2]);
            accY[i][3] = fmaf(a.x, wv0.w, accY[i][3]); accY[i][3] = fmaf(a.y, wv1.w, accY[i][3]);
            accY[i][3] = fmaf(a.z, wv2.w, accY[i][3]); accY[i][3] = fmaf(a.w, wv3.w, accY[i][3]);
        }
    }
#pragma unroll
    for (int i = 0; i < 4; i++)
        *(float4*)(g_y + (long long)(row0 + r1 + i) * YW + cg) =
            make_float4(accY[i][0], accY[i][1], accY[i][2], accY[i][3]);
}

// ---------------------------------------------------------------------------
// k_layer<LAST>: 128 thr / 32 rows / 22.5KB / 7 blocks/SM / grid 1024.
//   t_ne = lrelu(mean_k y[pred] + ne_b1)        (64-wide gather, no matmul!)
//   t_sf = lrelu(feat@sf_w1 + sf_b1)
//   hn   = t @ [ne_w2; sf_w2] + (ne_b2+sf_b2)
//   LAST:  g_h = hn (no relu).  else: hn=relu(hn); g_y = hn @ ne_w1.
// ---------------------------------------------------------------------------
template <bool LAST>
__global__ void __launch_bounds__(128, 7)
k_layer(int lo,
        const int*   __restrict__ pred,
        const float* __restrict__ feat,
        const float* __restrict__ ne_w1, const float* __restrict__ ne_b1,
        const float* __restrict__ ne_w2, const float* __restrict__ ne_b2,
        const float* __restrict__ sf_w1, const float* __restrict__ sf_b1,
        const float* __restrict__ sf_w2, const float* __restrict__ sf_b2)
{
    extern __shared__ float smem[];
    float* s_t   = smem;            // 32*128 = 4096 (t, later hn)
    float* s_ft  = smem + 4096;     // 32*32 = 1024
    float* s_b1  = smem + 5120;     // 128 [ne_b1 | sf_b1]
    float* s_b2  = smem + 5248;     // 128
    int*   s_pred = (int*)(smem + 5376);  // 256
    // 5632 floats = 22528 B

    const int tid  = threadIdx.x;
    const int row0 = blockIdx.x * 32;

    // ---- preload ----
    for (int i = tid; i < 256; i += 128) {
        int r = i >> 3, c4 = i & 7;
        ((float4*)(s_ft + r * 32))[c4] =
            *((const float4*)(feat + (long long)(lo + row0 + r) * 32) + c4);
    }
    for (int i = tid; i < 256; i += 128)
        s_pred[i] = pred[(long long)row0 * KK + i];
    if (tid < 128) {
        s_b1[tid] = (tid < 64) ? ne_b1[tid] : sf_b1[tid - 64];
        s_b2[tid] = ne_b2[tid] + sf_b2[tid];
    }
    __syncthreads();

    // ---- gather-mean of y (64-wide) + fused bias + lrelu -> t_ne ----
    float4* t4 = (float4*)s_t;      // pitch 32 float4
#pragma unroll
    for (int j = 0; j < 4; j++) {
        int task = tid + j * 128;
        int r = task >> 4, c4 = task & 15;
        const int* pr = s_pred + r * 8;
        float x = 0.f, y = 0.f, z = 0.f, s = 0.f;
#pragma unroll
        for (int k = 0; k < 8; k++) {
            const float4 v = *((const float4*)(g_y + (long long)pr[k] * YW) + c4);
            x += v.x; y += v.y; z += v.z; s += v.w;
        }
        const int c = c4 * 4;
        float4 o;
        o.x = lrelu(x * 0.125f + s_b1[c + 0]);
        o.y = lrelu(y * 0.125f + s_b1[c + 1]);
        o.z = lrelu(z * 0.125f + s_b1[c + 2]);
        o.w = lrelu(s * 0.125f + s_b1[c + 3]);
        t4[r * 32 + c4] = o;        // t_ne cols 0..63
    }

    const int w = tid >> 5, l = tid & 31;
    const int r0 = w * 8;
    const int r1 = r0 + (l >> 4) * 4;
    const int cg = (l & 15) * 4;

    // ---- t_sf = lrelu(feat @ sf_w1 + b): k=32, weights from global ----
    {
        float accB[4][4];
#pragma unroll
        for (int i = 0; i < 4; i++)
#pragma unroll
            for (int c = 0; c < 4; c++) accB[i][c] = 0.f;
#pragma unroll 2
        for (int k = 0; k < 32; k += 4) {
            float4 wv0 = *(const float4*)(sf_w1 + (k + 0) * 64 + cg);
            float4 wv1 = *(const float4*)(sf_w1 + (k + 1) * 64 + cg);
            float4 wv2 = *(const float4*)(sf_w1 + (k + 2) * 64 + cg);
            float4 wv3 = *(const float4*)(sf_w1 + (k + 3) * 64 + cg);
#pragma unroll
            for (int i = 0; i < 4; i++) {
                float4 a = *(const float4*)(s_ft + (r1 + i) * 32 + k);
                accB[i][0] = fmaf(a.x, wv0.x, accB[i][0]); accB[i][0] = fmaf(a.y, wv1.x, accB[i][0]);
                accB[i][0] = fmaf(a.z, wv2.x, accB[i][0]); accB[i][0] = fmaf(a.w, wv3.x, accB[i][0]);
                accB[i][1] = fmaf(a.x, wv0.y, accB[i][1]); accB[i][1] = fmaf(a.y, wv1.y, accB[i][1]);
                accB[i][1] = fmaf(a.z, wv2.y, accB[i][1]); accB[i][1] = fmaf(a.w, wv3.y, accB[i][1]);
                accB[i][2] = fmaf(a.x, wv0.z, accB[i][2]); accB[i][2] = fmaf(a.y, wv1.z, accB[i][2]);
                accB[i][2] = fmaf(a.z, wv2.z, accB[i][2]); accB[i][2] = fmaf(a.w, wv3.z, accB[i][2]);
                accB[i][3] = fmaf(a.x, wv0.w, accB[i][3]); accB[i][3] = fmaf(a.y, wv1.w, accB[i][3]);
                accB[i][3] = fmaf(a.z, wv2.w, accB[i][3]); accB[i][3] = fmaf(a.w, wv3.w, accB[i][3]);
            }
        }
#pragma unroll
        for (int i = 0; i < 4; i++) {
            float4 o;
            o.x = lrelu(accB[i][0] + s_b1[64 + cg + 0]);
            o.y = lrelu(accB[i][1] + s_b1[64 + cg + 1]);
            o.z = lrelu(accB[i][2] + s_b1[64 + cg + 2]);
            o.w = lrelu(accB[i][3] + s_b1[64 + cg + 3]);
            *(float4*)(s_t + (r1 + i) * 128 + 64 + cg) = o;   // t_sf cols 64..127
        }
    }
    __syncthreads();   // t complete block-wide (gather writes are block-striped)

    // ---- stage 2: hn = t @ [ne_w2; sf_w2], warp-own 8 rows, c0 = l*4 ----
    const int c0 = l * 4;
    float acc[8][4];
#pragma unroll
    for (int r = 0; r < 8; r++) { acc[r][0] = acc[r][1] = acc[r][2] = acc[r][3] = 0.f; }

#pragma unroll 2
    for (int k = 0; k < 64; k += 4) {
        float4 wv0 = *(const float4*)(ne_w2 + (k + 0) * 128 + c0);
        float4 wv1 = *(const float4*)(ne_w2 + (k + 1) * 128 + c0);
        float4 wv2 = *(const float4*)(ne_w2 + (k + 2) * 128 + c0);
        float4 wv3 = *(const float4*)(ne_w2 + (k + 3) * 128 + c0);
#pragma unroll
        for (int r = 0; r < 8; r++) {
            float4 a = *(const float4*)(s_t + (r0 + r) * 128 + k);
            acc[r][0] = fmaf(a.x, wv0.x, acc[r][0]); acc[r][0] = fmaf(a.y, wv1.x, acc[r][0]);
            acc[r][0] = fmaf(a.z, wv2.x, acc[r][0]); acc[r][0] = fmaf(a.w, wv3.x, acc[r][0]);
            acc[r][1] = fmaf(a.x, wv0.y, acc[r][1]); acc[r][1] = fmaf(a.y, wv1.y, acc[r][1]);
            acc[r][1] = fmaf(a.z, wv2.y, acc[r][1]); acc[r][1] = fmaf(a.w, wv3.y, acc[r][1]);
            acc[r][2] = fmaf(a.x, wv0.z, acc[r][2]); acc[r][2] = fmaf(a.y, wv1.z, acc[r][2]);
            acc[r][2] = fmaf(a.z, wv2.z, acc[r][2]); acc[r][2] = fmaf(a.w, wv3.z, acc[r][2]);
            acc[r][3] = fmaf(a.x, wv0.w, acc[r][3]); acc[r][3] = fmaf(a.y, wv1.w, acc[r][3]);
            acc[r][3] = fmaf(a.z, wv2.w, acc[r][3]); acc[r][3] = fmaf(a.w, wv3.w, acc[r][3]);
        }
    }
#pragma unroll 2
    for (int k = 0; k < 64; k += 4) {
        float4 wv0 = *(const float4*)(sf_w2 + (k + 0) * 128 + c0);
        float4 wv1 = *(const float4*)(sf_w2 + (k + 1) * 128 + c0);
        float4 wv2 = *(const float4*)(sf_w2 + (k + 2) * 128 + c0);
        float4 wv3 = *(const float4*)(sf_w2 + (k + 3) * 128 + c0);
#pragma unroll
        for (int r = 0; r < 8; r++) {
            float4 a = *(const float4*)(s_t + (r0 + r) * 128 + 64 + k);
            acc[r][0] = fmaf(a.x, wv0.x, acc[r][0]); acc[r][0] = fmaf(a.y, wv1.x, acc[r][0]);
            acc[r][0] = fmaf(a.z, wv2.x, acc[r][0]); acc[r][0] = fmaf(a.w, wv3.x, acc[r][0]);
            acc[r][1] = fmaf(a.x, wv0.y, acc[r][1]); acc[r][1] = fmaf(a.y, wv1.y, acc[r][1]);
            acc[r][1] = fmaf(a.z, wv2.y, acc[r][1]); acc[r][1] = fmaf(a.w, wv3.y, acc[r][1]);
            acc[r][2] = fmaf(a.x, wv0.z, acc[r][2]); acc[r][2] = fmaf(a.y, wv1.z, acc[r][2]);
            acc[r][2] = fmaf(a.z, wv2.z, acc[r][2]); acc[r][2] = fmaf(a.w, wv3.z, acc[r][2]);
            acc[r][3] = fmaf(a.x, wv0.w, acc[r][3]); acc[r][3] = fmaf(a.y, wv1.w, acc[r][3]);
            acc[r][3] = fmaf(a.z, wv2.w, acc[r][3]); acc[r][3] = fmaf(a.w, wv3.w, acc[r][3]);
        }
    }

    if (LAST) {
        // final layer: h = hn + b2 (NO relu; is_po==1) -> g_h
#pragma unroll
        for (int r = 0; r < 8; r++) {
            float4 o;
            o.x = acc[r][0] + s_b2[c0 + 0];
            o.y = acc[r][1] + s_b2[c0 + 1];
            o.z = acc[r][2] + s_b2[c0 + 2];
            o.w = acc[r][3] + s_b2[c0 + 3];
            *(float4*)(g_h + (long long)(lo + row0 + r0 + r) * HH + c0) = o;
        }
    } else {
        // hn = relu(hn + b2) -> overwrite own t rows (own-row readers done)
#pragma unroll
        for (int r = 0; r < 8; r++) {
            float4 o;
            o.x = relu_(acc[r][0] + s_b2[c0 + 0]);
            o.y = relu_(acc[r][1] + s_b2[c0 + 1]);
            o.z = relu_(acc[r][2] + s_b2[c0 + 2]);
            o.w = relu_(acc[r][3] + s_b2[c0 + 3]);
            *(float4*)(s_t + (r0 + r) * 128 + c0) = o;
        }
        __syncwarp();

        // y = hn @ ne_w1 -> g_y (half-warp map, k=128 over own rows)
        float accY[4][4];
#pragma unroll
        for (int i = 0; i < 4; i++)
#pragma unroll
            for (int c = 0; c < 4; c++) accY[i][c] = 0.f;
#pragma unroll 2
        for (int k = 0; k < 128; k += 4) {
            float4 wv0 = *(const float4*)(ne_w1 + (k + 0) * 64 + cg);
            float4 wv1 = *(const float4*)(ne_w1 + (k + 1) * 64 + cg);
            float4 wv2 = *(const float4*)(ne_w1 + (k + 2) * 64 + cg);
            float4 wv3 = *(const float4*)(ne_w1 + (k + 3) * 64 + cg);
#pragma unroll
            for (int i = 0; i < 4; i++) {
                float4 a = *(const float4*)(s_t + (r1 + i) * 128 + k);
                accY[i][0] = fmaf(a.x, wv0.x, accY[i][0]); accY[i][0] = fmaf(a.y, wv1.x, accY[i][0]);
                accY[i][0] = fmaf(a.z, wv2.x, accY[i][0]); accY[i][0] = fmaf(a.w, wv3.x, accY[i][0]);
                accY[i][1] = fmaf(a.x, wv0.y, accY[i][1]); accY[i][1] = fmaf(a.y, wv1.y, accY[i][1]);
                accY[i][1] = fmaf(a.z, wv2.y, accY[i][1]); accY[i][1] = fmaf(a.w, wv3.y, accY[i][1]);
                accY[i][2] = fmaf(a.x, wv0.z, accY[i][2]); accY[i][2] = fmaf(a.y, wv1.z, accY[i][2]);
                accY[i][2] = fmaf(a.z, wv2.z, accY[i][2]); accY[i][2] = fmaf(a.w, wv3.z, accY[i][2]);
                accY[i][3] = fmaf(a.x, wv0.w, accY[i][3]); accY[i][3] = fmaf(a.y, wv1.w, accY[i][3]);
                accY[i][3] = fmaf(a.z, wv2.w, accY[i][3]); accY[i][3] = fmaf(a.w, wv3.w, accY[i][3]);
            }
        }
#pragma unroll
        for (int i = 0; i < 4; i++)
            *(float4*)(g_y + (long long)(lo + row0 + r1 + i) * YW + cg) =
                make_float4(accY[i][0], accY[i][1], accY[i][2], accY[i][3]);
    }
}

// ---------------------------------------------------------------------------
// Final head (unchanged; reads g_h layer-15 rows)
// ---------------------------------------------------------------------------
__global__ void __launch_bounds__(256, 1)
k_final(const float* __restrict__ PO,
        const float* __restrict__ gl_w1, const float* __restrict__ gl_b1,
        const float* __restrict__ gl_w2, const float* __restrict__ gl_b2,
        const float* __restrict__ out_w1, const float* __restrict__ out_b1,
        const float* __restrict__ out_w2, const float* __restrict__ out_b2,
        float* __restrict__ out)
{
    extern __shared__ float smem[];
    float* s_x   = smem;             // 64*256
    float* s_w   = s_x + 16384;      // 64*128
    float* s_t   = s_w + 8192;       // 64*132
    float* s_g1  = s_t + 8448;       // 64*64
    float* s_gb2 = s_g1 + 4096;      // 128
    float* s_ob1 = s_gb2 + 128;      // 128
    float* s_ow2 = s_ob1 + 128;      // 128

    const int tid  = threadIdx.x;
    const int row0 = blockIdx.x * 64;
    const long long gnn0 = (long long)(LL - 1) * PP * HH;

    for (int i = tid; i < 2048; i += 256)
        ((float4*)s_w)[i] = ((const float4*)gl_w2)[i];
    for (int i = tid; i < 128; i += 256) {
        s_gb2[i] = gl_b2[i];
        s_ob1[i] = out_b1[i];
        s_ow2[i] = out_w2[i];
    }
    for (int i = tid; i < 64 * 64; i += 256) {
        int r = i >> 6, c = i & 63;
        s_g1[i] = lrelu(PO[row0 + r] * gl_w1[c] + gl_b1[c]);
    }
    for (int i = tid; i < 2048; i += 256) {
        int r = i >> 5, c4 = i & 31;
        float4 v = *((const float4*)(g_h + gnn0 + (long long)(row0 + r) * HH) + c4);
        *((float4*)(s_x + r * 256) + c4) = v;
    }
    __syncthreads();

    const int w = tid >> 5, l = tid & 31;
    const int r0 = w * 8, c0 = l * 4;

    {
        float acc[8][4];
#pragma unroll
        for (int r = 0; r < 8; r++) { acc[r][0] = acc[r][1] = acc[r][2] = acc[r][3] = 0.f; }
#pragma unroll 4
        for (int k = 0; k < 64; k += 2) {
            float4 w0  = *(const float4*)(s_w + k * 128 + c0);
            float4 w1v = *(const float4*)(s_w + (k + 1) * 128 + c0);
#pragma unroll
            for (int r = 0; r < 8; r++) {
                float2 a = *(const float2*)(s_g1 + (r0 + r) * 64 + k);
                acc[r][0] = fmaf(a.x, w0.x, acc[r][0]); acc[r][0] = fmaf(a.y, w1v.x, acc[r][0]);
                acc[r][1] = fmaf(a.x, w0.y, acc[r][1]); acc[r][1] = fmaf(a.y, w1v.y, acc[r][1]);
                acc[r][2] = fmaf(a.x, w0.z, acc[r][2]); acc[r][2] = fmaf(a.y, w1v.z, acc[r][2]);
                acc[r][3] = fmaf(a.x, w0.w, acc[r][3]); acc[r][3] = fmaf(a.y, w1v.w, acc[r][3]);
            }
        }
#pragma unroll
        for (int r = 0; r < 8; r++) {
            float4 o;
            o.x = acc[r][0] + s_gb2[c0 + 0];
            o.y = acc[r][1] + s_gb2[c0 + 1];
            o.z = acc[r][2] + s_gb2[c0 + 2];
            o.w = acc[r][3] + s_gb2[c0 + 3];
            *(float4*)(s_x + (r0 + r) * 256 + 128 + c0) = o;
        }
    }

    float acc[8][4];
#pragma unroll
    for (int r = 0; r < 8; r++) { acc[r][0] = acc[r][1] = acc[r][2] = acc[r][3] = 0.f; }
    for (int kt = 0; kt < 4; kt++) {
        __syncthreads();
        const float4* src = (const float4*)(out_w1 + kt * 64 * 128);
        for (int i = tid; i < 2048; i += 256) ((float4*)s_w)[i] = src[i];
        __syncthreads();
#pragma unroll 4
        for (int k = 0; k < 64; k += 2) {
            float4 w0  = *(const float4*)(s_w + k * 128 + c0);
            float4 w1v = *(const float4*)(s_w + (k + 1) * 128 + c0);
#pragma unroll
            for (int r = 0; r < 8; r++) {
                float2 a = *(const float2*)(s_x + (r0 + r) * 256 + kt * 64 + k);
                acc[r][0] = fmaf(a.x, w0.x, acc[r][0]); acc[r][0] = fmaf(a.y, w1v.x, acc[r][0]);
                acc[r][1] = fmaf(a.x, w0.y, acc[r][1]); acc[r][1] = fmaf(a.y, w1v.y, acc[r][1]);
                acc[r][2] = fmaf(a.x, w0.z, acc[r][2]); acc[r][2] = fmaf(a.y, w1v.z, acc[r][2]);
                acc[r][3] = fmaf(a.x, w0.w, acc[r][3]); acc[r][3] = fmaf(a.y, w1v.w, acc[r][3]);
            }
        }
    }
#pragma unroll
    for (int r = 0; r < 8; r++) {
        float* t = s_t + (r0 + r) * 132;
        t[c0 + 0] = lrelu(acc[r][0] + s_ob1[c0 + 0]);
        t[c0 + 1] = lrelu(acc[r][1] + s_ob1[c0 + 1]);
        t[c0 + 2] = lrelu(acc[r][2] + s_ob1[c0 + 2]);
        t[c0 + 3] = lrelu(acc[r][3] + s_ob1[c0 + 3]);
    }
    __syncthreads();

    if (tid < 64) {
        float s = out_b2[0];
        const float* t = s_t + tid * 132;
#pragma unroll 8
        for (int k = 0; k < 128; k++) s = fmaf(t[k], s_ow2[k], s);
        out[row0 + tid] = s;
    }
}

// ---------------------------------------------------------------------------
extern "C" void kernel_launch(void* const* d_in, const int* in_sizes, int n_in,
                              void* d_out, int out_size)
{
    // Disambiguate input ordering via in_sizes[3] (pred=3932160 vs pi_w1=64).
    int idx_pred, idx_ispo, wbase;
    if (in_sizes[3] == (LL - 1) * PP * KK) { idx_pred = 3; idx_ispo = 4; wbase = 5; }
    else                                   { idx_pred = 23; idx_ispo = 24; wbase = 3; }
    (void)idx_ispo;

    const float* delay  = (const float*)d_in[0];
    const float* feat   = (const float*)d_in[1];
    const float* PO     = (const float*)d_in[2];
    const int*   pred   = (const int*)d_in[idx_pred];
    const float* pi_w1  = (const float*)d_in[wbase + 0];
    const float* pi_b1  = (const float*)d_in[wbase + 1];
    const float* pi_w2  = (const float*)d_in[wbase + 2];
    const float* pi_b2  = (const float*)d_in[wbase + 3];
    const float* ne_w1  = (const float*)d_in[wbase + 4];
    const float* ne_b1  = (const float*)d_in[wbase + 5];
    const float* ne_w2  = (const float*)d_in[wbase + 6];
    const float* ne_b2  = (const float*)d_in[wbase + 7];
    const float* sf_w1  = (const float*)d_in[wbase + 8];
    const float* sf_b1  = (const float*)d_in[wbase + 9];
    const float* sf_w2  = (const float*)d_in[wbase + 10];
    const float* sf_b2  = (const float*)d_in[wbase + 11];
    const float* gl_w1  = (const float*)d_in[wbase + 12];
    const float* gl_b1  = (const float*)d_in[wbase + 13];
    const float* gl_w2  = (const float*)d_in[wbase + 14];
    const float* gl_b2  = (const float*)d_in[wbase + 15];
    const float* out_w1 = (const float*)d_in[wbase + 16];
    const float* out_b1 = (const float*)d_in[wbase + 17];
    const float* out_w2 = (const float*)d_in[wbase + 18];
    const float* out_b2 = (const float*)d_in[wbase + 19];
    float* out = (float*)d_out;

    const size_t sh_init  = (size_t)(4096 + 8192 + 128 + 8192) * 4;   // 82,432 B
    const size_t sh_layer = (size_t)5632 * 4;                          // 22,528 B
    const size_t sh_final = (size_t)(16384 + 8192 + 8448 + 4096 + 128 + 128 + 128) * 4;

    cudaFuncSetAttribute(k_init,  cudaFuncAttributeMaxDynamicSharedMemorySize, (int)sh_init);
    cudaFuncSetAttribute(k_layer<false>, cudaFuncAttributeMaxDynamicSharedMemorySize, (int)sh_layer);
    cudaFuncSetAttribute(k_layer<true>,  cudaFuncAttributeMaxDynamicSharedMemorySize, (int)sh_layer);
    cudaFuncSetAttribute(k_final, cudaFuncAttributeMaxDynamicSharedMemorySize, (int)sh_final);

    k_init<<<PP / 64, 256, sh_init>>>(delay, pi_w1, pi_b1, pi_w2, pi_b2, ne_w1);
    for (int i = 1; i < LL; i++) {
        const int* pl = pred + (long long)(i - 1) * PP * KK;
        if (i < LL - 1)
            k_layer<false><<<PP / 32, 128, sh_layer>>>(i * PP, pl, feat,
                ne_w1, ne_b1, ne_w2, ne_b2, sf_w1, sf_b1, sf_w2, sf_b2);
        else
            k_layer<true><<<PP / 32, 128, sh_layer>>>(i * PP, pl, feat,
                ne_w1, ne_b1, ne_w2, ne_b2, sf_w1, sf_b1, sf_w2, sf_b2);
    }
    k_final<<<PP / 64, 256, sh_final>>>(PO, gl_w1, gl_b1, gl_w2, gl_b2,
                                        out_w1, out_b1, out_w2, out_b2, out);
}